// round 4
// baseline (speedup 1.0000x reference)
#include <cuda_runtime.h>
#include <math.h>

#define L_SEQ 256
#define B_SZ  512
#define KIN   15
#define KST   512
#define NLX   1536
#define NTOK  (L_SEQ*B_SZ)   // 131072
#define NB    128            // persistent CTAs (<=148 SMs -> all resident)
#define PAD   34             // smem weight row pad (even -> aligned float2)

// ---------------- scratch (device globals; no allocation) ----------------
__device__ float g_xe[(size_t)NTOK*KST];
__device__ float g_Lx[(size_t)NTOK*NLX];
__device__ float g_states[(size_t)NTOK*KST];
__device__ float g_ty[(size_t)(NTOK-B_SZ)*KST];
__device__ float g_h  [B_SZ*KST];
__device__ float g_hA [B_SZ*KST];
__device__ float g_hB [B_SZ*KST];
__device__ float g_acc[B_SZ*KST];
__device__ float g_zg [B_SZ*KST];
__device__ float g_u  [B_SZ*KST];
__device__ unsigned g_bar_count = 0;
__device__ volatile unsigned g_bar_gen = 0;

__device__ __forceinline__ float sigmoidf_(float x) { return 1.f/(1.f+expf(-x)); }

// software grid barrier (all NB CTAs guaranteed resident: 1 CTA/SM via smem)
__device__ __forceinline__ void grid_sync() {
    __syncthreads();
    if (threadIdx.x == 0) {
        __threadfence();
        unsigned g = g_bar_gen;
        if (atomicAdd(&g_bar_count, 1u) == (unsigned)(NB - 1)) {
            g_bar_count = 0;
            __threadfence();
            g_bar_gen = g + 1u;
        } else {
            while (g_bar_gen == g) { __nanosleep(40); }
            __threadfence();
        }
    }
    __syncthreads();
}

// ---------------- xe = tanh(x @ Win^T + bin) ----------------
__global__ void embed_kernel(const float* __restrict__ seq,
                             const float* __restrict__ Win,
                             const float* __restrict__ bin) {
    int tok = blockIdx.x;
    __shared__ float xs[KIN];
    if (threadIdx.x < KIN) xs[threadIdx.x] = seq[(size_t)tok*16 + threadIdx.x];
    __syncthreads();
    for (int j = threadIdx.x; j < KST; j += blockDim.x) {
        float s = bin[j];
        const float* wr = Win + j*KIN;
        #pragma unroll
        for (int i = 0; i < KIN; i++) s += xs[i]*wr[i];
        g_xe[(size_t)tok*KST + j] = tanhf(s);
    }
}

// ---------------- generic fp32 GEMM: C = act(A[MxK] @ B[NxK]^T) ----------------
template<bool TANH>
__global__ void __launch_bounds__(256) gemm_nt(const float* __restrict__ A,
                                               const float* __restrict__ B,
                                               float* __restrict__ C,
                                               int M, int N, int K) {
    __shared__ float As[16][68];
    __shared__ float Bs[16][68];
    int bm = blockIdx.x*64, bn = blockIdx.y*64;
    int tid = threadIdx.x;
    int tx = tid & 15, ty = tid >> 4;
    int lr = tid >> 2;
    int lc = (tid & 3) << 2;
    float acc[4][4] = {};
    const float* Ap = A + (size_t)(bm+lr)*K + lc;
    const float* Bp = B + (size_t)(bn+lr)*K + lc;
    for (int k0 = 0; k0 < K; k0 += 16) {
        float4 av = *(const float4*)(Ap + k0);
        float4 bv = *(const float4*)(Bp + k0);
        As[lc+0][lr]=av.x; As[lc+1][lr]=av.y; As[lc+2][lr]=av.z; As[lc+3][lr]=av.w;
        Bs[lc+0][lr]=bv.x; Bs[lc+1][lr]=bv.y; Bs[lc+2][lr]=bv.z; Bs[lc+3][lr]=bv.w;
        __syncthreads();
        #pragma unroll
        for (int kk = 0; kk < 16; kk++) {
            float4 a = *(const float4*)&As[kk][ty<<2];
            float4 b = *(const float4*)&Bs[kk][tx<<2];
            acc[0][0]+=a.x*b.x; acc[0][1]+=a.x*b.y; acc[0][2]+=a.x*b.z; acc[0][3]+=a.x*b.w;
            acc[1][0]+=a.y*b.x; acc[1][1]+=a.y*b.y; acc[1][2]+=a.y*b.z; acc[1][3]+=a.y*b.w;
            acc[2][0]+=a.z*b.x; acc[2][1]+=a.z*b.y; acc[2][2]+=a.z*b.z; acc[2][3]+=a.z*b.w;
            acc[3][0]+=a.w*b.x; acc[3][1]+=a.w*b.y; acc[3][2]+=a.w*b.z; acc[3][3]+=a.w*b.w;
        }
        __syncthreads();
    }
    #pragma unroll
    for (int i = 0; i < 4; i++) {
        size_t row = (size_t)(bm + (ty<<2) + i)*N + bn + (tx<<2);
        #pragma unroll
        for (int j = 0; j < 4; j++) {
            float v = acc[i][j];
            if (TANH) v = tanhf(v);
            C[row + j] = v;
        }
    }
}

// ---------------- persistent recurrence kernel ----------------
// 128 CTAs x 256 thr. CTA tile: 64 batch rows x 32 state cols.
// Per stage: phase A = gate GEMM (z,r slabs) -> z, u=r*h ; grid_sync ;
//            phase B = (u)@Wlin^T GEMM + RK4 epilogue ; grid_sync.
// Weights for this CTA's j-tile cached in smem once (3 slabs, [k][j] w/ pad).
__global__ void __launch_bounds__(256) recur_kernel(
    const float* __restrict__ seq, const float* __restrict__ state0,
    const float* __restrict__ Wg, const float* __restrict__ bg,
    const float* __restrict__ Wlin, const float* __restrict__ blin)
{
    extern __shared__ float smem[];
    float* Wz_s = smem;                 // KST*PAD
    float* Wr_s = Wz_s + KST*PAD;
    float* Wl_s = Wr_s + KST*PAD;
    float* As   = Wl_s + KST*PAD;       // 16*68

    int tid = threadIdx.x;
    int b0 = (blockIdx.x & 7) * 64;
    int j0 = (blockIdx.x >> 3) * 32;

    // cache weight slabs ([k][j] layout, coalesced gmem reads)
    for (int idx = tid; idx < 32*KST; idx += 256) {
        int k = idx & (KST-1), jj = idx >> 9;
        Wz_s[k*PAD + jj] = Wg  [(size_t)(j0+jj)*KST       + k];
        Wr_s[k*PAD + jj] = Wg  [(size_t)(KST + j0+jj)*KST + k];
        Wl_s[k*PAD + jj] = Wlin[(size_t)(j0+jj)*KST       + k];
    }
    // init h
    for (int idx = blockIdx.x*256 + tid; idx < B_SZ*KST; idx += NB*256)
        g_h[idx] = state0[idx & (KST-1)];
    grid_sync();

    int tx  = tid & 15;
    int ty4 = (tid >> 4) << 2;
    int lr  = tid >> 2;
    int lc  = (tid & 3) << 2;

    for (int t = 0; t < L_SEQ; ++t) {
        const float* Lxt = g_Lx + (size_t)t*B_SZ*NLX;
        #pragma unroll 1
        for (int s = 1; s <= 4; ++s) {
            const float* hin = (s==1) ? g_h : (s==2 ? g_hA : (s==3 ? g_hB : g_hA));

            // ---- phase A: gates ----
            {
                float az[4][2] = {}, ar[4][2] = {};
                for (int k0 = 0; k0 < KST; k0 += 16) {
                    float4 av = *(const float4*)&hin[(size_t)(b0+lr)*KST + k0 + lc];
                    As[(lc+0)*68 + lr]=av.x; As[(lc+1)*68 + lr]=av.y;
                    As[(lc+2)*68 + lr]=av.z; As[(lc+3)*68 + lr]=av.w;
                    __syncthreads();
                    #pragma unroll
                    for (int kk = 0; kk < 16; kk++) {
                        float4 a  = *(const float4*)&As[kk*68 + ty4];
                        float2 bz = *(const float2*)&Wz_s[(k0+kk)*PAD + (tx<<1)];
                        float2 br = *(const float2*)&Wr_s[(k0+kk)*PAD + (tx<<1)];
                        az[0][0]+=a.x*bz.x; az[0][1]+=a.x*bz.y;
                        az[1][0]+=a.y*bz.x; az[1][1]+=a.y*bz.y;
                        az[2][0]+=a.z*bz.x; az[2][1]+=a.z*bz.y;
                        az[3][0]+=a.w*bz.x; az[3][1]+=a.w*bz.y;
                        ar[0][0]+=a.x*br.x; ar[0][1]+=a.x*br.y;
                        ar[1][0]+=a.y*br.x; ar[1][1]+=a.y*br.y;
                        ar[2][0]+=a.z*br.x; ar[2][1]+=a.z*br.y;
                        ar[3][0]+=a.w*br.x; ar[3][1]+=a.w*br.y;
                    }
                    __syncthreads();
                }
                #pragma unroll
                for (int i = 0; i < 4; i++) {
                    int b = b0 + ty4 + i;
                    const float* lxrow = Lxt + (size_t)b*NLX;
                    #pragma unroll
                    for (int jj = 0; jj < 2; jj++) {
                        int j = j0 + (tx<<1) + jj;
                        size_t idx = (size_t)b*KST + j;
                        float hv = hin[idx];
                        float z = sigmoidf_(lxrow[j]       + az[i][jj] + bg[j]);
                        float r = sigmoidf_(lxrow[KST + j] + ar[i][jj] + bg[KST + j]);
                        g_zg[idx] = z;
                        g_u [idx] = r * hv;
                    }
                }
            }
            grid_sync();

            // ---- phase B: lin GEMM on u + RK4 update ----
            {
                float al[4][2] = {};
                for (int k0 = 0; k0 < KST; k0 += 16) {
                    float4 av = *(const float4*)&g_u[(size_t)(b0+lr)*KST + k0 + lc];
                    As[(lc+0)*68 + lr]=av.x; As[(lc+1)*68 + lr]=av.y;
                    As[(lc+2)*68 + lr]=av.z; As[(lc+3)*68 + lr]=av.w;
                    __syncthreads();
                    #pragma unroll
                    for (int kk = 0; kk < 16; kk++) {
                        float4 a  = *(const float4*)&As[kk*68 + ty4];
                        float2 bl = *(const float2*)&Wl_s[(k0+kk)*PAD + (tx<<1)];
                        al[0][0]+=a.x*bl.x; al[0][1]+=a.x*bl.y;
                        al[1][0]+=a.y*bl.x; al[1][1]+=a.y*bl.y;
                        al[2][0]+=a.z*bl.x; al[2][1]+=a.z*bl.y;
                        al[3][0]+=a.w*bl.x; al[3][1]+=a.w*bl.y;
                    }
                    __syncthreads();
                }
                #pragma unroll
                for (int i = 0; i < 4; i++) {
                    int b = b0 + ty4 + i;
                    float dt = (t > 0) ? seq[((size_t)(t-1)*B_SZ + b)*16 + 15] : 0.f;
                    const float* lxrow = Lxt + (size_t)b*NLX;
                    #pragma unroll
                    for (int jj = 0; jj < 2; jj++) {
                        int j = j0 + (tx<<1) + jj;
                        size_t idx = (size_t)b*KST + j;
                        float hv = hin[idx];
                        float z  = g_zg[idx];
                        float kv = z*(tanhf(lxrow[2*KST + j] + al[i][jj] + blin[j]) - hv);
                        if (s == 1)      { g_acc[idx]  = kv;      g_hA[idx] = g_h[idx] + dt*0.5f*kv; }
                        else if (s == 2) { g_acc[idx] += 2.f*kv;  g_hB[idx] = g_h[idx] + dt*0.5f*kv; }
                        else if (s == 3) { g_acc[idx] += 2.f*kv;  g_hA[idx] = g_h[idx] + dt*kv; }
                        else {
                            float hn = g_h[idx] + dt*(g_acc[idx] + kv)*(1.f/6.f);
                            g_h[idx] = hn;
                            g_states[(size_t)t*B_SZ*KST + idx] = hn;
                        }
                    }
                }
            }
            grid_sync();
        }
    }
}

// ---------------- out[1..255] = g_ty @ Ly2^T ----------------
__global__ void yout_kernel(const float* __restrict__ Ly2, float* __restrict__ out) {
    __shared__ float l2s[8*KST];
    int tid = threadIdx.x;
    for (int i = tid; i < 8*KST; i += 256) l2s[i] = Ly2[i];
    __syncthreads();
    int warp = tid >> 5, lane = tid & 31;
    int tok = blockIdx.x*8 + warp;
    const float* tr = g_ty + (size_t)tok*KST;
    float p[8] = {};
    for (int k = lane; k < KST; k += 32) {
        float tv = tr[k];
        #pragma unroll
        for (int o = 0; o < 8; o++) p[o] += tv*l2s[o*KST + k];
    }
    #pragma unroll
    for (int o = 0; o < 8; o++)
        #pragma unroll
        for (int off = 16; off; off >>= 1)
            p[o] += __shfl_xor_sync(0xffffffffu, p[o], off);
    if (lane == 0) {
        float* op = out + (size_t)(tok + B_SZ)*8;
        #pragma unroll
        for (int o = 0; o < 8; o++) op[o] = p[o];
    }
}

// ---------------- out[0] = Ly(h0) broadcast over batch ----------------
__global__ void y0_kernel(const float* __restrict__ state0,
                          const float* __restrict__ Ly1,
                          const float* __restrict__ Ly2,
                          float* __restrict__ out) {
    __shared__ float h0s[KST];
    __shared__ float tys[KST];
    __shared__ float y0s[8];
    int tid = threadIdx.x;
    for (int j = tid; j < KST; j += 256) h0s[j] = state0[j];
    __syncthreads();
    for (int j = tid; j < KST; j += 256) {
        float s = 0.f;
        const float* lr = Ly1 + (size_t)j*KST;
        for (int k = 0; k < KST; k++) s += h0s[k]*lr[k];
        tys[j] = tanhf(s);
    }
    __syncthreads();
    if (tid < 8) {
        float s = 0.f;
        const float* lr = Ly2 + (size_t)tid*KST;
        for (int k = 0; k < KST; k++) s += tys[k]*lr[k];
        y0s[tid] = s;
    }
    __syncthreads();
    for (int i = tid; i < B_SZ*8; i += 256) out[i] = y0s[i & 7];
}

// ---------------- launch ----------------
extern "C" void kernel_launch(void* const* d_in, const int* in_sizes, int n_in,
                              void* d_out, int out_size) {
    const float* seq    = (const float*)d_in[0];
    const float* state0 = (const float*)d_in[1];
    const float* Win    = (const float*)d_in[2];
    const float* bin    = (const float*)d_in[3];
    const float* Wx     = (const float*)d_in[4];
    const float* Wg     = (const float*)d_in[5];
    const float* bg     = (const float*)d_in[6];
    const float* Wlin   = (const float*)d_in[7];
    const float* blin   = (const float*)d_in[8];
    const float* Ly1    = (const float*)d_in[9];
    const float* Ly2    = (const float*)d_in[10];
    float* out = (float*)d_out;

    float *xe, *Lx, *states, *ty;
    cudaGetSymbolAddress((void**)&xe,     g_xe);
    cudaGetSymbolAddress((void**)&Lx,     g_Lx);
    cudaGetSymbolAddress((void**)&states, g_states);
    cudaGetSymbolAddress((void**)&ty,     g_ty);

    const int smem_bytes = (3*KST*PAD + 16*68) * (int)sizeof(float);  // 213 KB
    cudaFuncSetAttribute(recur_kernel, cudaFuncAttributeMaxDynamicSharedMemorySize, smem_bytes);

    embed_kernel<<<NTOK, 128>>>(seq, Win, bin);
    gemm_nt<false><<<dim3(NTOK/64, NLX/64), 256>>>(xe, Wx, Lx, NTOK, NLX, KST);

    recur_kernel<<<NB, 256, smem_bytes>>>(seq, state0, Wg, bg, Wlin, blin);

    gemm_nt<true><<<dim3((NTOK - B_SZ)/64, KST/64), 256>>>(states, Ly1, ty, NTOK - B_SZ, KST, KST);
    yout_kernel<<<(NTOK - B_SZ)/8, 256>>>(Ly2, out);
    y0_kernel<<<1, 256>>>(state0, Ly1, Ly2, out);
}

// round 5
// speedup vs baseline: 1.4266x; 1.4266x over previous
#include <cuda_runtime.h>
#include <math.h>

#define L_SEQ 256
#define B_SZ  512
#define KIN   15
#define KST   512
#define NLX   1536
#define NTOK  (L_SEQ*B_SZ)   // 131072
#define NB    128            // persistent CTAs (<=148 SMs -> all resident)
#define PAD   34             // smem weight row pad (floats, even -> aligned float2)
#define ADUP  66             // dup-A row stride in float2 units

typedef unsigned long long ull;

// ---------------- scratch (device globals; no allocation) ----------------
__device__ float g_xe[(size_t)NTOK*KST];
__device__ float g_Lx[(size_t)NTOK*NLX];
__device__ float g_states[(size_t)NTOK*KST];
__device__ float g_ty[(size_t)(NTOK-B_SZ)*KST];
__device__ float g_h  [B_SZ*KST];
__device__ float g_hA [B_SZ*KST];
__device__ float g_hB [B_SZ*KST];
__device__ float g_acc[B_SZ*KST];
__device__ float g_zg [B_SZ*KST];
__device__ float g_u  [B_SZ*KST];
__device__ unsigned g_bar_count = 0;
__device__ volatile unsigned g_bar_gen = 0;

// ---------------- packed fp32x2 helpers (Blackwell FFMA2) ----------------
__device__ __forceinline__ void ffma2(ull& d, ull a, ull b) {
    asm("fma.rn.f32x2 %0, %1, %2, %3;" : "=l"(d) : "l"(a), "l"(b), "l"(d));
}
__device__ __forceinline__ ull pack2(float x, float y) {
    ull r; asm("mov.b64 %0, {%1, %2};" : "=l"(r) : "f"(x), "f"(y)); return r;
}
__device__ __forceinline__ float2 unpack2(ull v) {
    float2 f; asm("mov.b64 {%0, %1}, %2;" : "=f"(f.x), "=f"(f.y) : "l"(v)); return f;
}

// fast activations (MUFU-based, ~1e-6 rel err, saturating at +-inf)
__device__ __forceinline__ float fsigmoid(float x) { return 1.f/(1.f + __expf(-x)); }
__device__ __forceinline__ float ftanh(float x) {
    float e = __expf(2.f*x);
    return 1.f - __fdividef(2.f, e + 1.f);
}

// software grid barrier (all NB CTAs resident: 1 CTA/SM via smem footprint)
__device__ __forceinline__ void grid_sync() {
    __syncthreads();
    if (threadIdx.x == 0) {
        __threadfence();
        unsigned g = g_bar_gen;
        if (atomicAdd(&g_bar_count, 1u) == (unsigned)(NB - 1)) {
            g_bar_count = 0;
            __threadfence();
            g_bar_gen = g + 1u;
        } else {
            while (g_bar_gen == g) { __nanosleep(40); }
            __threadfence();
        }
    }
    __syncthreads();
}

// ---------------- xe = tanh(x @ Win^T + bin) ----------------
__global__ void embed_kernel(const float* __restrict__ seq,
                             const float* __restrict__ Win,
                             const float* __restrict__ bin) {
    int tok = blockIdx.x;
    __shared__ float xs[KIN];
    if (threadIdx.x < KIN) xs[threadIdx.x] = seq[(size_t)tok*16 + threadIdx.x];
    __syncthreads();
    for (int j = threadIdx.x; j < KST; j += blockDim.x) {
        float s = bin[j];
        const float* wr = Win + j*KIN;
        #pragma unroll
        for (int i = 0; i < KIN; i++) s += xs[i]*wr[i];
        g_xe[(size_t)tok*KST + j] = ftanh(s);
    }
}

// ---------------- fp32x2 GEMM: C = act(A[MxK] @ B[NxK]^T), 64x64 tile ----------------
template<bool TANH>
__global__ void __launch_bounds__(256) gemm_nt(const float* __restrict__ A,
                                               const float* __restrict__ B,
                                               float* __restrict__ C,
                                               int M, int N, int K) {
    __shared__ float2 As2[16*ADUP];   // dup pairs (v,v), row=k, col=i
    __shared__ float  Bs [16*68];     // row=k, col=n
    int bm = blockIdx.x*64, bn = blockIdx.y*64;
    int tid = threadIdx.x;
    int tx  = tid & 15;
    int ty4 = (tid >> 4) << 2;
    int lr  = tid >> 2;
    int lc  = (tid & 3) << 2;
    ull acc2[4][2];
    #pragma unroll
    for (int i = 0; i < 4; i++) { acc2[i][0] = 0ull; acc2[i][1] = 0ull; }

    const float* Ap = A + (size_t)(bm+lr)*K + lc;
    const float* Bp = B + (size_t)(bn+lr)*K + lc;
    for (int k0 = 0; k0 < K; k0 += 16) {
        float4 av = *(const float4*)(Ap + k0);
        float4 bv = *(const float4*)(Bp + k0);
        As2[(lc+0)*ADUP + lr] = make_float2(av.x, av.x);
        As2[(lc+1)*ADUP + lr] = make_float2(av.y, av.y);
        As2[(lc+2)*ADUP + lr] = make_float2(av.z, av.z);
        As2[(lc+3)*ADUP + lr] = make_float2(av.w, av.w);
        Bs[(lc+0)*68 + lr]=bv.x; Bs[(lc+1)*68 + lr]=bv.y;
        Bs[(lc+2)*68 + lr]=bv.z; Bs[(lc+3)*68 + lr]=bv.w;
        __syncthreads();
        #pragma unroll
        for (int kk = 0; kk < 16; kk++) {
            ull b0 = *(const ull*)&Bs[kk*68 + (tx<<2)];
            ull b1 = *(const ull*)&Bs[kk*68 + (tx<<2) + 2];
            #pragma unroll
            for (int q = 0; q < 4; q++) {
                ull aq = *(const ull*)&As2[kk*ADUP + ty4 + q];
                ffma2(acc2[q][0], aq, b0);
                ffma2(acc2[q][1], aq, b1);
            }
        }
        __syncthreads();
    }
    #pragma unroll
    for (int i = 0; i < 4; i++) {
        size_t row = (size_t)(bm + ty4 + i)*N + bn + (tx<<2);
        #pragma unroll
        for (int p = 0; p < 2; p++) {
            float2 v = unpack2(acc2[i][p]);
            if (TANH) { v.x = ftanh(v.x); v.y = ftanh(v.y); }
            C[row + 2*p + 0] = v.x;
            C[row + 2*p + 1] = v.y;
        }
    }
}

// ---------------- persistent recurrence kernel ----------------
// 128 CTAs x 256 thr. CTA tile: 64 batch rows x 32 state cols.
// Per stage: phase A = gate GEMM (z,r slabs) -> z, u=r*h ; grid_sync ;
//            phase B = u @ Wlin^T GEMM + RK4 epilogue ; grid_sync.
// Weight slabs for this CTA's j-tile cached in smem once for all 1024 stages.
__global__ void __launch_bounds__(256) recur_kernel(
    const float* __restrict__ seq, const float* __restrict__ state0,
    const float* __restrict__ Wg, const float* __restrict__ bg,
    const float* __restrict__ Wlin, const float* __restrict__ blin)
{
    extern __shared__ float smem[];
    float*  Wz_s = smem;                       // KST*PAD floats
    float*  Wr_s = Wz_s + KST*PAD;
    float*  Wl_s = Wr_s + KST*PAD;
    float2* As2  = (float2*)(Wl_s + KST*PAD);  // 16*ADUP float2 (dup A)

    int tid = threadIdx.x;
    int b0 = (blockIdx.x & 7) * 64;
    int j0 = (blockIdx.x >> 3) * 32;

    // cache weight slabs ([k][j] layout, coalesced gmem reads)
    for (int idx = tid; idx < 32*KST; idx += 256) {
        int k = idx & (KST-1), jj = idx >> 9;
        Wz_s[k*PAD + jj] = Wg  [(size_t)(j0+jj)*KST       + k];
        Wr_s[k*PAD + jj] = Wg  [(size_t)(KST + j0+jj)*KST + k];
        Wl_s[k*PAD + jj] = Wlin[(size_t)(j0+jj)*KST       + k];
    }
    // init h
    for (int idx = blockIdx.x*256 + tid; idx < B_SZ*KST; idx += NB*256)
        g_h[idx] = state0[idx & (KST-1)];
    grid_sync();

    int tx  = tid & 15;
    int ty4 = (tid >> 4) << 2;
    int lr  = tid >> 2;
    int lc  = (tid & 3) << 2;

    for (int t = 0; t < L_SEQ; ++t) {
        const float* Lxt = g_Lx + (size_t)t*B_SZ*NLX;
        #pragma unroll 1
        for (int s = 1; s <= 4; ++s) {
            const float* hin = (s==1) ? g_h : (s==2 ? g_hA : (s==3 ? g_hB : g_hA));

            // ---- phase A: gate GEMM (z,r) ----
            {
                ull az2[4] = {0ull,0ull,0ull,0ull};
                ull ar2[4] = {0ull,0ull,0ull,0ull};
                for (int k0 = 0; k0 < KST; k0 += 16) {
                    float4 av = *(const float4*)&hin[(size_t)(b0+lr)*KST + k0 + lc];
                    As2[(lc+0)*ADUP + lr] = make_float2(av.x, av.x);
                    As2[(lc+1)*ADUP + lr] = make_float2(av.y, av.y);
                    As2[(lc+2)*ADUP + lr] = make_float2(av.z, av.z);
                    As2[(lc+3)*ADUP + lr] = make_float2(av.w, av.w);
                    __syncthreads();
                    #pragma unroll
                    for (int kk = 0; kk < 16; kk++) {
                        ull bz = *(const ull*)&Wz_s[(k0+kk)*PAD + (tx<<1)];
                        ull br = *(const ull*)&Wr_s[(k0+kk)*PAD + (tx<<1)];
                        #pragma unroll
                        for (int q = 0; q < 4; q++) {
                            ull aq = *(const ull*)&As2[kk*ADUP + ty4 + q];
                            ffma2(az2[q], aq, bz);
                            ffma2(ar2[q], aq, br);
                        }
                    }
                    __syncthreads();
                }
                #pragma unroll
                for (int i = 0; i < 4; i++) {
                    int b = b0 + ty4 + i;
                    const float* lxrow = Lxt + (size_t)b*NLX;
                    float2 az = unpack2(az2[i]);
                    float2 ar = unpack2(ar2[i]);
                    #pragma unroll
                    for (int jj = 0; jj < 2; jj++) {
                        int j = j0 + (tx<<1) + jj;
                        size_t idx = (size_t)b*KST + j;
                        float hv = hin[idx];
                        float azv = jj ? az.y : az.x;
                        float arv = jj ? ar.y : ar.x;
                        float z = fsigmoid(lxrow[j]       + azv + bg[j]);
                        float r = fsigmoid(lxrow[KST + j] + arv + bg[KST + j]);
                        g_zg[idx] = z;
                        g_u [idx] = r * hv;
                    }
                }
            }
            grid_sync();

            // ---- phase B: lin GEMM on u + RK4 update ----
            {
                ull al2[4] = {0ull,0ull,0ull,0ull};
                for (int k0 = 0; k0 < KST; k0 += 16) {
                    float4 av = *(const float4*)&g_u[(size_t)(b0+lr)*KST + k0 + lc];
                    As2[(lc+0)*ADUP + lr] = make_float2(av.x, av.x);
                    As2[(lc+1)*ADUP + lr] = make_float2(av.y, av.y);
                    As2[(lc+2)*ADUP + lr] = make_float2(av.z, av.z);
                    As2[(lc+3)*ADUP + lr] = make_float2(av.w, av.w);
                    __syncthreads();
                    #pragma unroll
                    for (int kk = 0; kk < 16; kk++) {
                        ull bl = *(const ull*)&Wl_s[(k0+kk)*PAD + (tx<<1)];
                        #pragma unroll
                        for (int q = 0; q < 4; q++) {
                            ull aq = *(const ull*)&As2[kk*ADUP + ty4 + q];
                            ffma2(al2[q], aq, bl);
                        }
                    }
                    __syncthreads();
                }
                #pragma unroll
                for (int i = 0; i < 4; i++) {
                    int b = b0 + ty4 + i;
                    float dt = (t > 0) ? seq[((size_t)(t-1)*B_SZ + b)*16 + 15] : 0.f;
                    const float* lxrow = Lxt + (size_t)b*NLX;
                    float2 al = unpack2(al2[i]);
                    #pragma unroll
                    for (int jj = 0; jj < 2; jj++) {
                        int j = j0 + (tx<<1) + jj;
                        size_t idx = (size_t)b*KST + j;
                        float hv = hin[idx];
                        float z  = g_zg[idx];
                        float alv = jj ? al.y : al.x;
                        float kv = z*(ftanh(lxrow[2*KST + j] + alv + blin[j]) - hv);
                        if (s == 1)      { g_acc[idx]  = kv;      g_hA[idx] = g_h[idx] + dt*0.5f*kv; }
                        else if (s == 2) { g_acc[idx] += 2.f*kv;  g_hB[idx] = g_h[idx] + dt*0.5f*kv; }
                        else if (s == 3) { g_acc[idx] += 2.f*kv;  g_hA[idx] = g_h[idx] + dt*kv; }
                        else {
                            float hn = g_h[idx] + dt*(g_acc[idx] + kv)*(1.f/6.f);
                            g_h[idx] = hn;
                            g_states[(size_t)t*B_SZ*KST + idx] = hn;
                        }
                    }
                }
            }
            grid_sync();
        }
    }
}

// ---------------- out[1..255] = g_ty @ Ly2^T ----------------
__global__ void yout_kernel(const float* __restrict__ Ly2, float* __restrict__ out) {
    __shared__ float l2s[8*KST];
    int tid = threadIdx.x;
    for (int i = tid; i < 8*KST; i += 256) l2s[i] = Ly2[i];
    __syncthreads();
    int warp = tid >> 5, lane = tid & 31;
    int tok = blockIdx.x*8 + warp;
    const float* tr = g_ty + (size_t)tok*KST;
    float p[8] = {};
    for (int k = lane; k < KST; k += 32) {
        float tv = tr[k];
        #pragma unroll
        for (int o = 0; o < 8; o++) p[o] += tv*l2s[o*KST + k];
    }
    #pragma unroll
    for (int o = 0; o < 8; o++)
        #pragma unroll
        for (int off = 16; off; off >>= 1)
            p[o] += __shfl_xor_sync(0xffffffffu, p[o], off);
    if (lane == 0) {
        float* op = out + (size_t)(tok + B_SZ)*8;
        #pragma unroll
        for (int o = 0; o < 8; o++) op[o] = p[o];
    }
}

// ---------------- out[0] = Ly(h0) broadcast over batch ----------------
__global__ void y0_kernel(const float* __restrict__ state0,
                          const float* __restrict__ Ly1,
                          const float* __restrict__ Ly2,
                          float* __restrict__ out) {
    __shared__ float h0s[KST];
    __shared__ float tys[KST];
    __shared__ float y0s[8];
    int tid = threadIdx.x;
    for (int j = tid; j < KST; j += 256) h0s[j] = state0[j];
    __syncthreads();
    for (int j = tid; j < KST; j += 256) {
        float s = 0.f;
        const float* lr = Ly1 + (size_t)j*KST;
        for (int k = 0; k < KST; k++) s += h0s[k]*lr[k];
        tys[j] = tanhf(s);
    }
    __syncthreads();
    if (tid < 8) {
        float s = 0.f;
        const float* lr = Ly2 + (size_t)tid*KST;
        for (int k = 0; k < KST; k++) s += tys[k]*lr[k];
        y0s[tid] = s;
    }
    __syncthreads();
    for (int i = tid; i < B_SZ*8; i += 256) out[i] = y0s[i & 7];
}

// ---------------- launch ----------------
extern "C" void kernel_launch(void* const* d_in, const int* in_sizes, int n_in,
                              void* d_out, int out_size) {
    const float* seq    = (const float*)d_in[0];
    const float* state0 = (const float*)d_in[1];
    const float* Win    = (const float*)d_in[2];
    const float* bin    = (const float*)d_in[3];
    const float* Wx     = (const float*)d_in[4];
    const float* Wg     = (const float*)d_in[5];
    const float* bg     = (const float*)d_in[6];
    const float* Wlin   = (const float*)d_in[7];
    const float* blin   = (const float*)d_in[8];
    const float* Ly1    = (const float*)d_in[9];
    const float* Ly2    = (const float*)d_in[10];
    float* out = (float*)d_out;

    float *xe, *Lx, *states, *ty;
    cudaGetSymbolAddress((void**)&xe,     g_xe);
    cudaGetSymbolAddress((void**)&Lx,     g_Lx);
    cudaGetSymbolAddress((void**)&states, g_states);
    cudaGetSymbolAddress((void**)&ty,     g_ty);

    const int smem_bytes = 3*KST*PAD*(int)sizeof(float) + 16*ADUP*(int)sizeof(float2);
    cudaFuncSetAttribute(recur_kernel, cudaFuncAttributeMaxDynamicSharedMemorySize, smem_bytes);

    embed_kernel<<<NTOK, 128>>>(seq, Win, bin);
    gemm_nt<false><<<dim3(NTOK/64, NLX/64), 256>>>(xe, Wx, Lx, NTOK, NLX, KST);

    recur_kernel<<<NB, 256, smem_bytes>>>(seq, state0, Wg, bg, Wlin, blin);

    gemm_nt<true><<<dim3((NTOK - B_SZ)/64, KST/64), 256>>>(states, Ly1, ty, NTOK - B_SZ, KST, KST);
    yout_kernel<<<(NTOK - B_SZ)/8, 256>>>(Ly2, out);
    y0_kernel<<<1, 256>>>(state0, Ly1, Ly2, out);
}

// round 6
// speedup vs baseline: 1.7536x; 1.2292x over previous
#include <cuda_runtime.h>
#include <math.h>

#define L_SEQ 256
#define B_SZ  512
#define KIN   15
#define KST   512
#define NLX   1536
#define NTOK  (L_SEQ*B_SZ)   // 131072
#define NB    128            // persistent CTAs (<=148 SMs -> all resident)
#define ADUP  66             // dup-A row stride in float2 units
#define A2SZ  (16*ADUP)      // one A-tile buffer in float2 units

typedef unsigned long long ull;

// ---------------- scratch (device globals; no allocation) ----------------
__device__ float g_xe[(size_t)NTOK*KST];
__device__ float g_Lx[(size_t)NTOK*NLX];
__device__ float g_states[(size_t)NTOK*KST];
__device__ float g_ty[(size_t)(NTOK-B_SZ)*KST];
__device__ float g_h  [B_SZ*KST];
__device__ float g_hA [B_SZ*KST];
__device__ float g_hB [B_SZ*KST];
__device__ float g_acc[B_SZ*KST];
__device__ float g_zg [B_SZ*KST];
__device__ float g_u  [B_SZ*KST];
__device__ unsigned g_bar_count = 0;
__device__ volatile unsigned g_bar_gen = 0;

// ---------------- packed fp32x2 helpers (Blackwell FFMA2) ----------------
__device__ __forceinline__ void ffma2(ull& d, ull a, ull b) {
    asm("fma.rn.f32x2 %0, %1, %2, %3;" : "=l"(d) : "l"(a), "l"(b), "l"(d));
}
__device__ __forceinline__ float2 unpack2(ull v) {
    float2 f; asm("mov.b64 {%0, %1}, %2;" : "=f"(f.x), "=f"(f.y) : "l"(v)); return f;
}

// fast activations (MUFU-based, ~1e-6 rel err, saturating at +-inf)
__device__ __forceinline__ float fsigmoid(float x) { return 1.f/(1.f + __expf(-x)); }
__device__ __forceinline__ float ftanh(float x) {
    float e = __expf(2.f*x);
    return 1.f - __fdividef(2.f, e + 1.f);
}

// software grid barrier (all NB CTAs resident: 1 CTA/SM via smem footprint)
__device__ __forceinline__ void grid_sync() {
    __syncthreads();
    if (threadIdx.x == 0) {
        __threadfence();
        unsigned g = g_bar_gen;
        if (atomicAdd(&g_bar_count, 1u) == (unsigned)(NB - 1)) {
            g_bar_count = 0;
            __threadfence();
            g_bar_gen = g + 1u;
        } else {
            while (g_bar_gen == g) { __nanosleep(40); }
            __threadfence();
        }
    }
    __syncthreads();
}

// ---------------- xe = tanh(x @ Win^T + bin) ----------------
__global__ void embed_kernel(const float* __restrict__ seq,
                             const float* __restrict__ Win,
                             const float* __restrict__ bin) {
    int tok = blockIdx.x;
    __shared__ float xs[KIN];
    if (threadIdx.x < KIN) xs[threadIdx.x] = seq[(size_t)tok*16 + threadIdx.x];
    __syncthreads();
    for (int j = threadIdx.x; j < KST; j += blockDim.x) {
        float s = bin[j];
        const float* wr = Win + j*KIN;
        #pragma unroll
        for (int i = 0; i < KIN; i++) s += xs[i]*wr[i];
        g_xe[(size_t)tok*KST + j] = ftanh(s);
    }
}

// ------- fp32x2 GEMM: C = act(A[MxK] @ B[NxK]^T), 64x64 tile, double-buffered -------
template<bool TANH>
__global__ void __launch_bounds__(256) gemm_nt(const float* __restrict__ A,
                                               const float* __restrict__ B,
                                               float* __restrict__ C,
                                               int M, int N, int K) {
    __shared__ float2 As2[2][A2SZ];   // dup pairs (v,v), row=k, col=i
    __shared__ float  Bs [2][16*68];  // row=k, col=n
    int bm = blockIdx.x*64, bn = blockIdx.y*64;
    int tid = threadIdx.x;
    int tx  = tid & 15;
    int ty4 = (tid >> 4) << 2;
    int lr  = tid >> 2;
    int lc  = (tid & 3) << 2;
    ull acc2[4][2];
    #pragma unroll
    for (int i = 0; i < 4; i++) { acc2[i][0] = 0ull; acc2[i][1] = 0ull; }

    const float* Ap = A + (size_t)(bm+lr)*K + lc;
    const float* Bp = B + (size_t)(bn+lr)*K + lc;

    // preload k0 = 0
    {
        float4 av = *(const float4*)(Ap);
        float4 bv = *(const float4*)(Bp);
        As2[0][(lc+0)*ADUP + lr] = make_float2(av.x, av.x);
        As2[0][(lc+1)*ADUP + lr] = make_float2(av.y, av.y);
        As2[0][(lc+2)*ADUP + lr] = make_float2(av.z, av.z);
        As2[0][(lc+3)*ADUP + lr] = make_float2(av.w, av.w);
        Bs[0][(lc+0)*68 + lr]=bv.x; Bs[0][(lc+1)*68 + lr]=bv.y;
        Bs[0][(lc+2)*68 + lr]=bv.z; Bs[0][(lc+3)*68 + lr]=bv.w;
    }
    __syncthreads();

    for (int k0 = 0; k0 < K; k0 += 16) {
        int buf = (k0 >> 4) & 1;
        bool more = (k0 + 16) < K;
        float4 avn, bvn;
        if (more) { avn = *(const float4*)(Ap + k0 + 16); bvn = *(const float4*)(Bp + k0 + 16); }
        const float2* a = As2[buf];
        const float*  b = Bs[buf];
        #pragma unroll
        for (int kk = 0; kk < 16; kk++) {
            ulonglong2 bb  = *(const ulonglong2*)&b[kk*68 + (tx<<2)];
            ulonglong2 a01 = *(const ulonglong2*)&a[kk*ADUP + ty4];
            ulonglong2 a23 = *(const ulonglong2*)&a[kk*ADUP + ty4 + 2];
            ffma2(acc2[0][0], a01.x, bb.x); ffma2(acc2[0][1], a01.x, bb.y);
            ffma2(acc2[1][0], a01.y, bb.x); ffma2(acc2[1][1], a01.y, bb.y);
            ffma2(acc2[2][0], a23.x, bb.x); ffma2(acc2[2][1], a23.x, bb.y);
            ffma2(acc2[3][0], a23.y, bb.x); ffma2(acc2[3][1], a23.y, bb.y);
        }
        if (more) {
            int nb = buf ^ 1;
            As2[nb][(lc+0)*ADUP + lr] = make_float2(avn.x, avn.x);
            As2[nb][(lc+1)*ADUP + lr] = make_float2(avn.y, avn.y);
            As2[nb][(lc+2)*ADUP + lr] = make_float2(avn.z, avn.z);
            As2[nb][(lc+3)*ADUP + lr] = make_float2(avn.w, avn.w);
            Bs[nb][(lc+0)*68 + lr]=bvn.x; Bs[nb][(lc+1)*68 + lr]=bvn.y;
            Bs[nb][(lc+2)*68 + lr]=bvn.z; Bs[nb][(lc+3)*68 + lr]=bvn.w;
        }
        __syncthreads();
    }
    #pragma unroll
    for (int i = 0; i < 4; i++) {
        size_t row = (size_t)(bm + ty4 + i)*N + bn + (tx<<2);
        #pragma unroll
        for (int p = 0; p < 2; p++) {
            float2 v = unpack2(acc2[i][p]);
            if (TANH) { v.x = ftanh(v.x); v.y = ftanh(v.y); }
            C[row + 2*p + 0] = v.x;
            C[row + 2*p + 1] = v.y;
        }
    }
}

// ---------------- persistent recurrence kernel ----------------
// 128 CTAs x 256 thr. CTA tile: 64 batch rows x 32 state cols.
// Smem: Wzr interleaved [z0 z1 r0 r1] per j-pair (one LDS.128 -> both gate operands),
// Wl as float2 pairs, dup-A double-buffered.
__global__ void __launch_bounds__(256) recur_kernel(
    const float* __restrict__ seq, const float* __restrict__ state0,
    const float* __restrict__ Wg, const float* __restrict__ bg,
    const float* __restrict__ Wlin, const float* __restrict__ blin)
{
    extern __shared__ char smem_raw[];
    float4* Wzr4 = (float4*)smem_raw;                          // KST*16 float4 = 131072 B
    float2* Wl2  = (float2*)(smem_raw + KST*16*16);            // KST*16 float2 =  65536 B
    float2* As2  = (float2*)(smem_raw + KST*16*16 + KST*16*8); // 2*A2SZ float2 =  16896 B

    int tid = threadIdx.x;
    int b0 = (blockIdx.x & 7) * 64;
    int j0 = (blockIdx.x >> 3) * 32;

    // cache weight slabs (coalesced gmem reads; scattered smem writes, one-time)
    {
        float* Wzr_f = (float*)Wzr4;
        float* Wl_f  = (float*)Wl2;
        for (int idx = tid; idx < 32*KST; idx += 256) {
            int k = idx & (KST-1), jj = idx >> 9;
            int p = jj >> 1, c = jj & 1;
            Wzr_f[(k*16 + p)*4 + c]     = Wg  [(size_t)(j0+jj)*KST       + k];
            Wzr_f[(k*16 + p)*4 + 2 + c] = Wg  [(size_t)(KST + j0+jj)*KST + k];
            Wl_f [(k*16 + p)*2 + c]     = Wlin[(size_t)(j0+jj)*KST       + k];
        }
    }
    // init h
    for (int idx = blockIdx.x*256 + tid; idx < B_SZ*KST; idx += NB*256)
        g_h[idx] = state0[idx & (KST-1)];
    grid_sync();

    int tx  = tid & 15;
    int ty4 = (tid >> 4) << 2;
    int lr  = tid >> 2;
    int lc  = (tid & 3) << 2;

    // hoist biases for this thread's two j columns
    int jA = j0 + (tx<<1);
    float bgz0 = bg[jA],       bgz1 = bg[jA+1];
    float bgr0 = bg[KST+jA],   bgr1 = bg[KST+jA+1];
    float bl0  = blin[jA],     bl1  = blin[jA+1];

    for (int t = 0; t < L_SEQ; ++t) {
        const float* Lxt = g_Lx + (size_t)t*B_SZ*NLX;
        #pragma unroll 1
        for (int s = 1; s <= 4; ++s) {
            const float* hin = (s==1) ? g_h : (s==2 ? g_hA : (s==3 ? g_hB : g_hA));

            // ---- phase A: gate GEMM (z,r fused via interleaved smem) ----
            {
                ull az2[4] = {0ull,0ull,0ull,0ull};
                ull ar2[4] = {0ull,0ull,0ull,0ull};
                const float* hrow = hin + (size_t)(b0+lr)*KST + lc;
                {
                    float4 av = *(const float4*)(hrow);
                    As2[(lc+0)*ADUP + lr] = make_float2(av.x, av.x);
                    As2[(lc+1)*ADUP + lr] = make_float2(av.y, av.y);
                    As2[(lc+2)*ADUP + lr] = make_float2(av.z, av.z);
                    As2[(lc+3)*ADUP + lr] = make_float2(av.w, av.w);
                }
                __syncthreads();
                for (int k0 = 0; k0 < KST; k0 += 16) {
                    int buf = (k0 >> 4) & 1;
                    bool more = (k0 + 16) < KST;
                    float4 avn;
                    if (more) avn = *(const float4*)(hrow + k0 + 16);
                    const float2* a = As2 + buf*A2SZ;
                    #pragma unroll
                    for (int kk = 0; kk < 16; kk++) {
                        ulonglong2 zr  = *(const ulonglong2*)(Wzr4 + (k0+kk)*16 + tx);
                        ulonglong2 a01 = *(const ulonglong2*)(a + kk*ADUP + ty4);
                        ulonglong2 a23 = *(const ulonglong2*)(a + kk*ADUP + ty4 + 2);
                        ffma2(az2[0], a01.x, zr.x); ffma2(ar2[0], a01.x, zr.y);
                        ffma2(az2[1], a01.y, zr.x); ffma2(ar2[1], a01.y, zr.y);
                        ffma2(az2[2], a23.x, zr.x); ffma2(ar2[2], a23.x, zr.y);
                        ffma2(az2[3], a23.y, zr.x); ffma2(ar2[3], a23.y, zr.y);
                    }
                    if (more) {
                        float2* dst = As2 + (buf^1)*A2SZ;
                        dst[(lc+0)*ADUP + lr] = make_float2(avn.x, avn.x);
                        dst[(lc+1)*ADUP + lr] = make_float2(avn.y, avn.y);
                        dst[(lc+2)*ADUP + lr] = make_float2(avn.z, avn.z);
                        dst[(lc+3)*ADUP + lr] = make_float2(avn.w, avn.w);
                    }
                    __syncthreads();
                }
                #pragma unroll
                for (int i = 0; i < 4; i++) {
                    int b = b0 + ty4 + i;
                    const float* lxrow = Lxt + (size_t)b*NLX;
                    float2 az = unpack2(az2[i]);
                    float2 ar = unpack2(ar2[i]);
                    size_t idx0 = (size_t)b*KST + jA;
                    float hv0 = hin[idx0], hv1 = hin[idx0+1];
                    float z0 = fsigmoid(lxrow[jA]         + az.x + bgz0);
                    float z1 = fsigmoid(lxrow[jA+1]       + az.y + bgz1);
                    float r0 = fsigmoid(lxrow[KST+jA]     + ar.x + bgr0);
                    float r1 = fsigmoid(lxrow[KST+jA+1]   + ar.y + bgr1);
                    g_zg[idx0]   = z0;  g_zg[idx0+1] = z1;
                    g_u [idx0]   = r0*hv0; g_u[idx0+1] = r1*hv1;
                }
            }
            grid_sync();

            // ---- phase B: lin GEMM on u + RK4 update ----
            {
                ull al2[4] = {0ull,0ull,0ull,0ull};
                const float* urow = g_u + (size_t)(b0+lr)*KST + lc;
                {
                    float4 av = *(const float4*)(urow);
                    As2[(lc+0)*ADUP + lr] = make_float2(av.x, av.x);
                    As2[(lc+1)*ADUP + lr] = make_float2(av.y, av.y);
                    As2[(lc+2)*ADUP + lr] = make_float2(av.z, av.z);
                    As2[(lc+3)*ADUP + lr] = make_float2(av.w, av.w);
                }
                __syncthreads();
                for (int k0 = 0; k0 < KST; k0 += 16) {
                    int buf = (k0 >> 4) & 1;
                    bool more = (k0 + 16) < KST;
                    float4 avn;
                    if (more) avn = *(const float4*)(urow + k0 + 16);
                    const float2* a = As2 + buf*A2SZ;
                    #pragma unroll
                    for (int kk = 0; kk < 16; kk++) {
                        ull bl = *(const ull*)(Wl2 + (k0+kk)*16 + tx);
                        ulonglong2 a01 = *(const ulonglong2*)(a + kk*ADUP + ty4);
                        ulonglong2 a23 = *(const ulonglong2*)(a + kk*ADUP + ty4 + 2);
                        ffma2(al2[0], a01.x, bl);
                        ffma2(al2[1], a01.y, bl);
                        ffma2(al2[2], a23.x, bl);
                        ffma2(al2[3], a23.y, bl);
                    }
                    if (more) {
                        float2* dst = As2 + (buf^1)*A2SZ;
                        dst[(lc+0)*ADUP + lr] = make_float2(avn.x, avn.x);
                        dst[(lc+1)*ADUP + lr] = make_float2(avn.y, avn.y);
                        dst[(lc+2)*ADUP + lr] = make_float2(avn.z, avn.z);
                        dst[(lc+3)*ADUP + lr] = make_float2(avn.w, avn.w);
                    }
                    __syncthreads();
                }
                #pragma unroll
                for (int i = 0; i < 4; i++) {
                    int b = b0 + ty4 + i;
                    float dt = (t > 0) ? seq[((size_t)(t-1)*B_SZ + b)*16 + 15] : 0.f;
                    const float* lxrow = Lxt + (size_t)b*NLX;
                    float2 al = unpack2(al2[i]);
                    size_t idx0 = (size_t)b*KST + jA;
                    #pragma unroll
                    for (int jj = 0; jj < 2; jj++) {
                        size_t idx = idx0 + jj;
                        float hv = hin[idx];
                        float z  = g_zg[idx];
                        float alv = jj ? al.y : al.x;
                        float blv = jj ? bl1 : bl0;
                        float kv = z*(ftanh(lxrow[2*KST + jA + jj] + alv + blv) - hv);
                        if (s == 1)      { g_acc[idx]  = kv;      g_hA[idx] = g_h[idx] + dt*0.5f*kv; }
                        else if (s == 2) { g_acc[idx] += 2.f*kv;  g_hB[idx] = g_h[idx] + dt*0.5f*kv; }
                        else if (s == 3) { g_acc[idx] += 2.f*kv;  g_hA[idx] = g_h[idx] + dt*kv; }
                        else {
                            float hn = g_h[idx] + dt*(g_acc[idx] + kv)*(1.f/6.f);
                            g_h[idx] = hn;
                            g_states[(size_t)t*B_SZ*KST + idx] = hn;
                        }
                    }
                }
            }
            grid_sync();
        }
    }
}

// ---------------- out[1..255] = g_ty @ Ly2^T ----------------
__global__ void yout_kernel(const float* __restrict__ Ly2, float* __restrict__ out) {
    __shared__ float l2s[8*KST];
    int tid = threadIdx.x;
    for (int i = tid; i < 8*KST; i += 256) l2s[i] = Ly2[i];
    __syncthreads();
    int warp = tid >> 5, lane = tid & 31;
    int tok = blockIdx.x*8 + warp;
    const float* tr = g_ty + (size_t)tok*KST;
    float p[8] = {};
    for (int k = lane; k < KST; k += 32) {
        float tv = tr[k];
        #pragma unroll
        for (int o = 0; o < 8; o++) p[o] += tv*l2s[o*KST + k];
    }
    #pragma unroll
    for (int o = 0; o < 8; o++)
        #pragma unroll
        for (int off = 16; off; off >>= 1)
            p[o] += __shfl_xor_sync(0xffffffffu, p[o], off);
    if (lane == 0) {
        float* op = out + (size_t)(tok + B_SZ)*8;
        #pragma unroll
        for (int o = 0; o < 8; o++) op[o] = p[o];
    }
}

// ---------------- out[0] = Ly(h0) broadcast over batch ----------------
__global__ void y0_kernel(const float* __restrict__ state0,
                          const float* __restrict__ Ly1,
                          const float* __restrict__ Ly2,
                          float* __restrict__ out) {
    __shared__ float h0s[KST];
    __shared__ float tys[KST];
    __shared__ float y0s[8];
    int tid = threadIdx.x;
    for (int j = tid; j < KST; j += 256) h0s[j] = state0[j];
    __syncthreads();
    for (int j = tid; j < KST; j += 256) {
        float s = 0.f;
        const float* lr = Ly1 + (size_t)j*KST;
        for (int k = 0; k < KST; k++) s += h0s[k]*lr[k];
        tys[j] = tanhf(s);
    }
    __syncthreads();
    if (tid < 8) {
        float s = 0.f;
        const float* lr = Ly2 + (size_t)tid*KST;
        for (int k = 0; k < KST; k++) s += tys[k]*lr[k];
        y0s[tid] = s;
    }
    __syncthreads();
    for (int i = tid; i < B_SZ*8; i += 256) out[i] = y0s[i & 7];
}

// ---------------- launch ----------------
extern "C" void kernel_launch(void* const* d_in, const int* in_sizes, int n_in,
                              void* d_out, int out_size) {
    const float* seq    = (const float*)d_in[0];
    const float* state0 = (const float*)d_in[1];
    const float* Win    = (const float*)d_in[2];
    const float* bin    = (const float*)d_in[3];
    const float* Wx     = (const float*)d_in[4];
    const float* Wg     = (const float*)d_in[5];
    const float* bg     = (const float*)d_in[6];
    const float* Wlin   = (const float*)d_in[7];
    const float* blin   = (const float*)d_in[8];
    const float* Ly1    = (const float*)d_in[9];
    const float* Ly2    = (const float*)d_in[10];
    float* out = (float*)d_out;

    float *xe, *Lx, *states, *ty;
    cudaGetSymbolAddress((void**)&xe,     g_xe);
    cudaGetSymbolAddress((void**)&Lx,     g_Lx);
    cudaGetSymbolAddress((void**)&states, g_states);
    cudaGetSymbolAddress((void**)&ty,     g_ty);

    const int smem_bytes = KST*16*16 + KST*16*8 + 2*A2SZ*8;   // 213504 B
    cudaFuncSetAttribute(recur_kernel, cudaFuncAttributeMaxDynamicSharedMemorySize, smem_bytes);

    embed_kernel<<<NTOK, 128>>>(seq, Win, bin);
    gemm_nt<false><<<dim3(NTOK/64, NLX/64), 256>>>(xe, Wx, Lx, NTOK, NLX, KST);

    recur_kernel<<<NB, 256, smem_bytes>>>(seq, state0, Wg, bg, Wlin, blin);

    gemm_nt<true><<<dim3((NTOK - B_SZ)/64, KST/64), 256>>>(states, Ly1, ty, NTOK - B_SZ, KST, KST);
    yout_kernel<<<(NTOK - B_SZ)/8, 256>>>(Ly2, out);
    y0_kernel<<<1, 256>>>(state0, Ly1, Ly2, out);
}

// round 8
// speedup vs baseline: 2.5319x; 1.4439x over previous
#include <cuda_runtime.h>
#include <cuda_bf16.h>
#include <math.h>
#include <stdint.h>

#define L_SEQ 256
#define B_SZ  512
#define KIN   15
#define KST   512
#define NLX   1536
#define NTOK  (L_SEQ*B_SZ)   // 131072
#define NBR   128            // persistent CTAs for recurrence
#define BSTR  520            // weight-slab row stride (bf16 elems)
#define ASTR  72             // A-chunk row stride (bf16 elems)

typedef unsigned long long ull;
typedef __nv_bfloat16 bf16;

// ---------------- scratch (device globals; no allocation) ----------------
__device__ __align__(16) bf16 g_xe_hi[(size_t)NTOK*KST];
__device__ __align__(16) bf16 g_xe_lo[(size_t)NTOK*KST];
__device__ float g_Lx[(size_t)NTOK*NLX];
__device__ __align__(16) bf16 g_st_hi[(size_t)NTOK*KST];
__device__ __align__(16) bf16 g_st_lo[(size_t)NTOK*KST];
__device__ float g_ty[(size_t)(NTOK-B_SZ)*KST];
__device__ float g_h  [B_SZ*KST];
__device__ float g_hA [B_SZ*KST];
__device__ float g_hB [B_SZ*KST];
__device__ float g_acc[B_SZ*KST];
__device__ float g_zg [B_SZ*KST];
__device__ __align__(16) bf16 g_hs_hi[B_SZ*KST];
__device__ __align__(16) bf16 g_hs_lo[B_SZ*KST];
__device__ __align__(16) bf16 g_us_hi[B_SZ*KST];
__device__ __align__(16) bf16 g_us_lo[B_SZ*KST];
__device__ unsigned g_bar_count = 0;
__device__ volatile unsigned g_bar_gen = 0;

// fast activations (MUFU-based, ~1e-6 rel err, saturating at +-inf)
__device__ __forceinline__ float fsigmoid(float x) { return 1.f/(1.f + __expf(-x)); }
__device__ __forceinline__ float ftanh(float x) {
    float e = __expf(2.f*x);
    return 1.f - __fdividef(2.f, e + 1.f);
}

// ---------------- warp-MMA primitives (sm_80+ baseline PTX) ----------------
__device__ __forceinline__ uint32_t smem_u32(const void* p) {
    uint32_t a;
    asm("{ .reg .u64 t; cvta.to.shared.u64 t, %1; cvt.u32.u64 %0, t; }" : "=r"(a) : "l"(p));
    return a;
}
__device__ __forceinline__ void ldsm4(uint32_t* r, uint32_t addr) {
    asm volatile("ldmatrix.sync.aligned.m8n8.x4.shared.b16 {%0,%1,%2,%3}, [%4];"
        : "=r"(r[0]), "=r"(r[1]), "=r"(r[2]), "=r"(r[3]) : "r"(addr));
}
__device__ __forceinline__ void mma16816(float* d, const uint32_t* a, uint32_t b0, uint32_t b1) {
    asm volatile("mma.sync.aligned.m16n8k16.row.col.f32.bf16.bf16.f32 "
        "{%0,%1,%2,%3}, {%4,%5,%6,%7}, {%8,%9}, {%0,%1,%2,%3};"
        : "+f"(d[0]), "+f"(d[1]), "+f"(d[2]), "+f"(d[3])
        : "r"(a[0]), "r"(a[1]), "r"(a[2]), "r"(a[3]), "r"(b0), "r"(b1));
}
__device__ __forceinline__ void split_store(bf16* hi, bf16* lo, size_t idx, float v) {
    bf16 h = __float2bfloat16(v);
    hi[idx] = h;
    lo[idx] = __float2bfloat16(v - __bfloat162float(h));
}

// software grid barrier across NBR CTAs (all resident: 1 CTA/SM via smem)
__device__ __forceinline__ void grid_sync() {
    __syncthreads();
    if (threadIdx.x == 0) {
        __threadfence();
        unsigned g = g_bar_gen;
        if (atomicAdd(&g_bar_count, 1u) == (unsigned)(NBR - 1)) {
            g_bar_count = 0;
            __threadfence();
            g_bar_gen = g + 1u;
        } else {
            while (g_bar_gen == g) { __nanosleep(40); }
            __threadfence();
        }
    }
    __syncthreads();
}

// ---------------- xe = tanh(x @ Win^T + bin), split to bf16 hi/lo ----------------
__global__ void embed_kernel(const float* __restrict__ seq,
                             const float* __restrict__ Win,
                             const float* __restrict__ bin) {
    int tok = blockIdx.x;
    __shared__ float xs[KIN];
    if (threadIdx.x < KIN) xs[threadIdx.x] = seq[(size_t)tok*16 + threadIdx.x];
    __syncthreads();
    for (int j = threadIdx.x; j < KST; j += blockDim.x) {
        float s = bin[j];
        const float* wr = Win + j*KIN;
        #pragma unroll
        for (int i = 0; i < KIN; i++) s += xs[i]*wr[i];
        split_store(g_xe_hi, g_xe_lo, (size_t)tok*KST + j, ftanh(s));
    }
}

// ---------------- split-bf16 GEMM: C = act(A @ B^T), tile 128x64, K=512 ----------------
// A given as bf16 hi/lo arrays [M][512]; B fp32 [N][512] split on the fly into smem.
// smem: B slab 64x520 hi/lo (133120 B) + A chunk 128x72 hi/lo (36864 B) = 169984 B.
#define GS_WHI  0
#define GS_WLO  66560
#define GS_AHI  133120
#define GS_ALO  151552
#define GS_SMEM 169984
template<int TANH>
__global__ void __launch_bounds__(256) gemm_split(
    const bf16* __restrict__ Ahi, const bf16* __restrict__ Alo,
    const float* __restrict__ B, float* __restrict__ C, int N)
{
    extern __shared__ char sm[];
    uint32_t smu = smem_u32(sm);
    int tid = threadIdx.x;
    int w = tid >> 5, lane = tid & 31;
    int bm = blockIdx.x*128, bn = blockIdx.y*64;

    // stage B slab: 64 rows x 512 k, split fp32 -> hi/lo bf16
    for (int e = tid; e < 64*KST; e += 256) {
        int n = e >> 9, k = e & (KST-1);
        float v = B[(size_t)(bn + n)*KST + k];
        bf16 h = __float2bfloat16(v);
        size_t o = (size_t)n*BSTR + k;
        ((bf16*)(sm + GS_WHI))[o] = h;
        ((bf16*)(sm + GS_WLO))[o] = __float2bfloat16(v - __bfloat162float(h));
    }

    float acc[8][4];
    #pragma unroll
    for (int i = 0; i < 8; i++) { acc[i][0]=0.f; acc[i][1]=0.f; acc[i][2]=0.f; acc[i][3]=0.f; }

    uint32_t a_off = ((uint32_t)(16*w + (lane & 15))*ASTR + ((lane >> 4) << 3)) * 2;
    uint32_t b_row = (lane & 7) + ((lane & 16) >> 1);
    uint32_t b_k8  = (lane & 8);

    int srow = tid >> 1, sks = (tid & 1)*32;   // A staging: 2 thr/row, 32 elems each
    const bf16* ahp = Ahi + (size_t)(bm + srow)*KST + sks;
    const bf16* alp = Alo + (size_t)(bm + srow)*KST + sks;
    uint32_t sdst = (uint32_t)(srow*ASTR + sks)*2;

    for (int c = 0; c < 8; c++) {
        __syncthreads();
        #pragma unroll
        for (int q = 0; q < 4; q++) {
            *(uint4*)(sm + GS_AHI + sdst + q*16) = *(const uint4*)((const char*)(ahp + c*64) + q*16);
            *(uint4*)(sm + GS_ALO + sdst + q*16) = *(const uint4*)((const char*)(alp + c*64) + q*16);
        }
        __syncthreads();
        #pragma unroll
        for (int ks = 0; ks < 4; ks++) {
            uint32_t ah[4], al[4];
            ldsm4(ah, smu + GS_AHI + a_off + ks*32);
            ldsm4(al, smu + GS_ALO + a_off + ks*32);
            uint32_t kb = (uint32_t)(c*64 + ks*16 + b_k8)*2;
            #pragma unroll
            for (int p = 0; p < 4; p++) {
                uint32_t bh[4], bl[4];
                uint32_t bo = (uint32_t)(16*p + b_row)*BSTR*2 + kb;
                ldsm4(bh, smu + GS_WHI + bo);
                ldsm4(bl, smu + GS_WLO + bo);
                mma16816(acc[2*p],   ah, bh[0], bh[1]);
                mma16816(acc[2*p+1], ah, bh[2], bh[3]);
                mma16816(acc[2*p],   ah, bl[0], bl[1]);
                mma16816(acc[2*p+1], ah, bl[2], bl[3]);
                mma16816(acc[2*p],   al, bh[0], bh[1]);
                mma16816(acc[2*p+1], al, bh[2], bh[3]);
            }
        }
    }

    int rowl = bm + 16*w + (lane >> 2);
    #pragma unroll
    for (int nt = 0; nt < 8; nt++) {
        int col = bn + 8*nt + 2*(lane & 3);
        #pragma unroll
        for (int rr = 0; rr < 2; rr++) {
            size_t ro = (size_t)(rowl + 8*rr)*N + col;
            float v0 = acc[nt][2*rr], v1 = acc[nt][2*rr+1];
            if (TANH) { v0 = ftanh(v0); v1 = ftanh(v1); }
            C[ro] = v0; C[ro + 1] = v1;
        }
    }
}

// ---------------- persistent recurrence kernel (warp-MMA, split-bf16) ----------------
// 128 CTAs x 256 thr. CTA: b0 = (cta&7)*64 rows, j = (cta>>3)*32 state cols.
// Phase A: gates tile 64x64 (32 z + 32 r cols) vs Wg slab; phase B: lin 64x32 vs Wlin.
#define RC_WAHI 0
#define RC_WALO 66560
#define RC_WBHI 133120
#define RC_WBLO 166400
#define RC_AHI  199680
#define RC_ALO  208896
#define RC_SMEM 218112
__global__ void __launch_bounds__(256, 1) recur_mma(
    const float* __restrict__ seq, const float* __restrict__ state0,
    const float* __restrict__ Wg, const float* __restrict__ bg,
    const float* __restrict__ Wlin, const float* __restrict__ blin)
{
    extern __shared__ char sm[];
    uint32_t smu = smem_u32(sm);
    int tid = threadIdx.x;
    int w = tid >> 5, lane = tid & 31;
    int cta = blockIdx.x;
    int b0 = (cta & 7)*64;
    int j0 = (cta >> 3)*32;

    // stage Wg slab (64 rows: 32 z + 32 r) and Wlin slab (32 rows), split hi/lo
    for (int e = tid; e < 64*KST; e += 256) {
        int n = e >> 9, k = e & (KST-1);
        int grow = (n < 32) ? (j0 + n) : (KST + j0 + n - 32);
        float v = Wg[(size_t)grow*KST + k];
        bf16 h = __float2bfloat16(v);
        size_t o = (size_t)n*BSTR + k;
        ((bf16*)(sm + RC_WAHI))[o] = h;
        ((bf16*)(sm + RC_WALO))[o] = __float2bfloat16(v - __bfloat162float(h));
    }
    for (int e = tid; e < 32*KST; e += 256) {
        int n = e >> 9, k = e & (KST-1);
        float v = Wlin[(size_t)(j0 + n)*KST + k];
        bf16 h = __float2bfloat16(v);
        size_t o = (size_t)n*BSTR + k;
        ((bf16*)(sm + RC_WBHI))[o] = h;
        ((bf16*)(sm + RC_WBLO))[o] = __float2bfloat16(v - __bfloat162float(h));
    }
    // init h + split
    for (int idx = cta*256 + tid; idx < B_SZ*KST; idx += NBR*256) {
        float h0 = state0[idx & (KST-1)];
        g_h[idx] = h0;
        split_store(g_hs_hi, g_hs_lo, idx, h0);
    }
    grid_sync();

    // per-warp geometry
    int mtA = w & 3, chA = w >> 2;          // phase A: 4 m-tiles x 2 col halves (z|r)
    int mtB = w & 3, coB = (w >> 2)*16;     // phase B: 4 m-tiles x 2 col-16 halves
    uint32_t a_offA = ((uint32_t)(16*mtA + (lane & 15))*ASTR + ((lane >> 4) << 3)) * 2;
    uint32_t a_offB = ((uint32_t)(16*mtB + (lane & 15))*ASTR + ((lane >> 4) << 3)) * 2;
    uint32_t b_row = (lane & 7) + ((lane & 16) >> 1);
    uint32_t b_k8  = (lane & 8);

    int srow = tid >> 2, sks = (tid & 3)*16;  // A staging: 4 thr/row, 16 elems each
    uint32_t sdst = (uint32_t)(srow*ASTR + sks)*2;

    #pragma unroll 1
    for (int t = 0; t < L_SEQ; ++t) {
        const float* Lxt = g_Lx + (size_t)t*B_SZ*NLX;
        #pragma unroll 1
        for (int s = 1; s <= 4; ++s) {
            const float* hin = (s==1) ? g_h : (s==2 ? g_hA : (s==3 ? g_hB : g_hA));

            // ================= phase A: gate GEMM (z,r) =================
            {
                float acc[4][4];
                #pragma unroll
                for (int i = 0; i < 4; i++) { acc[i][0]=0.f; acc[i][1]=0.f; acc[i][2]=0.f; acc[i][3]=0.f; }
                const bf16* shp = g_hs_hi + (size_t)(b0 + srow)*KST + sks;
                const bf16* slp = g_hs_lo + (size_t)(b0 + srow)*KST + sks;
                #pragma unroll 1
                for (int c = 0; c < 8; c++) {
                    __syncthreads();
                    *(uint4*)(sm + RC_AHI + sdst)      = *(const uint4*)((const char*)(shp + c*64));
                    *(uint4*)(sm + RC_AHI + sdst + 16) = *(const uint4*)((const char*)(shp + c*64) + 16);
                    *(uint4*)(sm + RC_ALO + sdst)      = *(const uint4*)((const char*)(slp + c*64));
                    *(uint4*)(sm + RC_ALO + sdst + 16) = *(const uint4*)((const char*)(slp + c*64) + 16);
                    __syncthreads();
                    #pragma unroll
                    for (int ks = 0; ks < 4; ks++) {
                        uint32_t ah[4], al[4];
                        ldsm4(ah, smu + RC_AHI + a_offA + ks*32);
                        ldsm4(al, smu + RC_ALO + a_offA + ks*32);
                        uint32_t kb = (uint32_t)(c*64 + ks*16 + b_k8)*2;
                        #pragma unroll
                        for (int p = 0; p < 2; p++) {
                            uint32_t bh[4], bl[4];
                            uint32_t bo = (uint32_t)(32*chA + 16*p + b_row)*BSTR*2 + kb;
                            ldsm4(bh, smu + RC_WAHI + bo);
                            ldsm4(bl, smu + RC_WALO + bo);
                            mma16816(acc[2*p],   ah, bh[0], bh[1]);
                            mma16816(acc[2*p+1], ah, bh[2], bh[3]);
                            mma16816(acc[2*p],   ah, bl[0], bl[1]);
                            mma16816(acc[2*p+1], ah, bl[2], bl[3]);
                            mma16816(acc[2*p],   al, bh[0], bh[1]);
                            mma16816(acc[2*p+1], al, bh[2], bh[3]);
                        }
                    }
                }
                // gate epilogue
                int rowl = b0 + 16*mtA + (lane >> 2);
                #pragma unroll
                for (int nt = 0; nt < 4; nt++) {
                    int jl = 8*nt + 2*(lane & 3);
                    #pragma unroll
                    for (int rr = 0; rr < 2; rr++) {
                        int row = rowl + 8*rr;
                        const float* lx = Lxt + (size_t)row*NLX;
                        #pragma unroll
                        for (int jj = 0; jj < 2; jj++) {
                            int j = j0 + jl + jj;
                            float a = acc[nt][2*rr + jj];
                            size_t idx = (size_t)row*KST + j;
                            if (chA == 0) {
                                g_zg[idx] = fsigmoid(a + lx[j] + bg[j]);
                            } else {
                                float r = fsigmoid(a + lx[KST + j] + bg[KST + j]);
                                split_store(g_us_hi, g_us_lo, idx, r * hin[idx]);
                            }
                        }
                    }
                }
            }
            grid_sync();

            // ================= phase B: lin GEMM + RK4 =================
            {
                float acc[2][4];
                #pragma unroll
                for (int i = 0; i < 2; i++) { acc[i][0]=0.f; acc[i][1]=0.f; acc[i][2]=0.f; acc[i][3]=0.f; }
                const bf16* shp = g_us_hi + (size_t)(b0 + srow)*KST + sks;
                const bf16* slp = g_us_lo + (size_t)(b0 + srow)*KST + sks;
                #pragma unroll 1
                for (int c = 0; c < 8; c++) {
                    __syncthreads();
                    *(uint4*)(sm + RC_AHI + sdst)      = *(const uint4*)((const char*)(shp + c*64));
                    *(uint4*)(sm + RC_AHI + sdst + 16) = *(const uint4*)((const char*)(shp + c*64) + 16);
                    *(uint4*)(sm + RC_ALO + sdst)      = *(const uint4*)((const char*)(slp + c*64));
                    *(uint4*)(sm + RC_ALO + sdst + 16) = *(const uint4*)((const char*)(slp + c*64) + 16);
                    __syncthreads();
                    #pragma unroll
                    for (int ks = 0; ks < 4; ks++) {
                        uint32_t ah[4], al[4];
                        ldsm4(ah, smu + RC_AHI + a_offB + ks*32);
                        ldsm4(al, smu + RC_ALO + a_offB + ks*32);
                        uint32_t kb = (uint32_t)(c*64 + ks*16 + b_k8)*2;
                        uint32_t bh[4], bl[4];
                        uint32_t bo = (uint32_t)(coB + b_row)*BSTR*2 + kb;
                        ldsm4(bh, smu + RC_WBHI + bo);
                        ldsm4(bl, smu + RC_WBLO + bo);
                        mma16816(acc[0], ah, bh[0], bh[1]);
                        mma16816(acc[1], ah, bh[2], bh[3]);
                        mma16816(acc[0], ah, bl[0], bl[1]);
                        mma16816(acc[1], ah, bl[2], bl[3]);
                        mma16816(acc[0], al, bh[0], bh[1]);
                        mma16816(acc[1], al, bh[2], bh[3]);
                    }
                }
                // RK4 epilogue
                int rowl = b0 + 16*mtB + (lane >> 2);
                #pragma unroll
                for (int rr = 0; rr < 2; rr++) {
                    int row = rowl + 8*rr;
                    float dt = (t > 0) ? seq[((size_t)(t-1)*B_SZ + row)*16 + 15] : 0.f;
                    const float* lx = Lxt + (size_t)row*NLX;
                    #pragma unroll
                    for (int nt = 0; nt < 2; nt++) {
                        int jl = coB + 8*nt + 2*(lane & 3);
                        #pragma unroll
                        for (int jj = 0; jj < 2; jj++) {
                            int j = j0 + jl + jj;
                            size_t idx = (size_t)row*KST + j;
                            float hv = hin[idx];
                            float kv = g_zg[idx] * (ftanh(acc[nt][2*rr + jj] + lx[2*KST + j] + blin[j]) - hv);
                            float ht;
                            if (s == 1)      { g_acc[idx]  = kv;      ht = g_h[idx] + dt*0.5f*kv; g_hA[idx] = ht; }
                            else if (s == 2) { g_acc[idx] += 2.f*kv;  ht = g_h[idx] + dt*0.5f*kv; g_hB[idx] = ht; }
                            else if (s == 3) { g_acc[idx] += 2.f*kv;  ht = g_h[idx] + dt*kv;      g_hA[idx] = ht; }
                            else {
                                ht = g_h[idx] + dt*(g_acc[idx] + kv)*(1.f/6.f);
                                g_h[idx] = ht;
                                split_store(g_st_hi, g_st_lo, (size_t)t*B_SZ*KST + idx, ht);
                            }
                            split_store(g_hs_hi, g_hs_lo, idx, ht);
                        }
                    }
                }
            }
            grid_sync();
        }
    }
}

// ---------------- out[1..255] = g_ty @ Ly2^T ----------------
__global__ void yout_kernel(const float* __restrict__ Ly2, float* __restrict__ out) {
    __shared__ float l2s[8*KST];
    int tid = threadIdx.x;
    for (int i = tid; i < 8*KST; i += 256) l2s[i] = Ly2[i];
    __syncthreads();
    int warp = tid >> 5, lane = tid & 31;
    int tok = blockIdx.x*8 + warp;
    const float* tr = g_ty + (size_t)tok*KST;
    float p[8] = {};
    for (int k = lane; k < KST; k += 32) {
        float tv = tr[k];
        #pragma unroll
        for (int o = 0; o < 8; o++) p[o] += tv*l2s[o*KST + k];
    }
    #pragma unroll
    for (int o = 0; o < 8; o++)
        #pragma unroll
        for (int off = 16; off; off >>= 1)
            p[o] += __shfl_xor_sync(0xffffffffu, p[o], off);
    if (lane == 0) {
        float* op = out + (size_t)(tok + B_SZ)*8;
        #pragma unroll
        for (int o = 0; o < 8; o++) op[o] = p[o];
    }
}

// ---------------- out[0] = Ly(h0) broadcast over batch ----------------
__global__ void y0_kernel(const float* __restrict__ state0,
                          const float* __restrict__ Ly1,
                          const float* __restrict__ Ly2,
                          float* __restrict__ out) {
    __shared__ float h0s[KST];
    __shared__ float tys[KST];
    __shared__ float y0s[8];
    int tid = threadIdx.x;
    for (int j = tid; j < KST; j += 256) h0s[j] = state0[j];
    __syncthreads();
    for (int j = tid; j < KST; j += 256) {
        float s = 0.f;
        const float* lr = Ly1 + (size_t)j*KST;
        for (int k = 0; k < KST; k++) s += h0s[k]*lr[k];
        tys[j] = tanhf(s);
    }
    __syncthreads();
    if (tid < 8) {
        float s = 0.f;
        const float* lr = Ly2 + (size_t)tid*KST;
        for (int k = 0; k < KST; k++) s += tys[k]*lr[k];
        y0s[tid] = s;
    }
    __syncthreads();
    for (int i = tid; i < B_SZ*8; i += 256) out[i] = y0s[i & 7];
}

// ---------------- launch ----------------
extern "C" void kernel_launch(void* const* d_in, const int* in_sizes, int n_in,
                              void* d_out, int out_size) {
    const float* seq    = (const float*)d_in[0];
    const float* state0 = (const float*)d_in[1];
    const float* Win    = (const float*)d_in[2];
    const float* bin    = (const float*)d_in[3];
    const float* Wx     = (const float*)d_in[4];
    const float* Wg     = (const float*)d_in[5];
    const float* bg     = (const float*)d_in[6];
    const float* Wlin   = (const float*)d_in[7];
    const float* blin   = (const float*)d_in[8];
    const float* Ly1    = (const float*)d_in[9];
    const float* Ly2    = (const float*)d_in[10];
    float* out = (float*)d_out;

    bf16 *xeh, *xel, *sth, *stl;
    float *Lx, *ty;
    cudaGetSymbolAddress((void**)&xeh, g_xe_hi);
    cudaGetSymbolAddress((void**)&xel, g_xe_lo);
    cudaGetSymbolAddress((void**)&sth, g_st_hi);
    cudaGetSymbolAddress((void**)&stl, g_st_lo);
    cudaGetSymbolAddress((void**)&Lx,  g_Lx);
    cudaGetSymbolAddress((void**)&ty,  g_ty);

    cudaFuncSetAttribute(recur_mma, cudaFuncAttributeMaxDynamicSharedMemorySize, RC_SMEM);
    cudaFuncSetAttribute(gemm_split<0>, cudaFuncAttributeMaxDynamicSharedMemorySize, GS_SMEM);
    cudaFuncSetAttribute(gemm_split<1>, cudaFuncAttributeMaxDynamicSharedMemorySize, GS_SMEM);

    embed_kernel<<<NTOK, 128>>>(seq, Win, bin);
    gemm_split<0><<<dim3(NTOK/128, NLX/64), 256, GS_SMEM>>>(xeh, xel, Wx, Lx, NLX);

    recur_mma<<<NBR, 256, RC_SMEM>>>(seq, state0, Wg, bg, Wlin, blin);

    gemm_split<1><<<dim3((NTOK - B_SZ)/128, KST/64), 256, GS_SMEM>>>(sth, stl, Ly1, ty, KST);
    yout_kernel<<<(NTOK - B_SZ)/8, 256>>>(Ly2, out);
    y0_kernel<<<1, 256>>>(state0, Ly1, Ly2, out);
}

// round 9
// speedup vs baseline: 2.9119x; 1.1501x over previous
#include <cuda_runtime.h>
#include <cuda_bf16.h>
#include <math.h>
#include <stdint.h>

#define L_SEQ 256
#define B_SZ  512
#define KIN   15
#define KST   512
#define NLX   1536
#define NTOK  (L_SEQ*B_SZ)   // 131072
#define NBR   128            // persistent CTAs for recurrence
#define BSTR  520            // weight-slab row stride (bf16 elems), 1040B rows (16B aligned, bank-safe)
#define ASTR  40             // A-chunk row stride (bf16 elems), 80B rows

typedef unsigned long long ull;
typedef __nv_bfloat16 bf16;

// ---------------- scratch (device globals; no allocation) ----------------
__device__ __align__(16) bf16 g_xe_hi[(size_t)NTOK*KST];
__device__ __align__(16) bf16 g_xe_lo[(size_t)NTOK*KST];
__device__ float g_Lx[(size_t)NTOK*NLX];
__device__ __align__(16) bf16 g_st_hi[(size_t)NTOK*KST];
__device__ __align__(16) bf16 g_st_lo[(size_t)NTOK*KST];
__device__ float g_ty[(size_t)(NTOK-B_SZ)*KST];
__device__ float g_h  [B_SZ*KST];
__device__ float g_hA [B_SZ*KST];
__device__ float g_hB [B_SZ*KST];
__device__ float g_acc[B_SZ*KST];
__device__ float g_zg [B_SZ*KST];
__device__ __align__(16) bf16 g_hs_hi[B_SZ*KST];
__device__ __align__(16) bf16 g_hs_lo[B_SZ*KST];
__device__ __align__(16) bf16 g_us_hi[B_SZ*KST];
__device__ __align__(16) bf16 g_us_lo[B_SZ*KST];
__device__ unsigned g_bar_count = 0;
__device__ volatile unsigned g_bar_gen = 0;

// fast activations (MUFU-based, ~1e-6 rel err, saturating at +-inf)
__device__ __forceinline__ float fsigmoid(float x) { return 1.f/(1.f + __expf(-x)); }
__device__ __forceinline__ float ftanh(float x) {
    float e = __expf(2.f*x);
    return 1.f - __fdividef(2.f, e + 1.f);
}

// ---------------- warp-MMA + async-copy primitives (sm_80+ baseline PTX) ----------------
__device__ __forceinline__ uint32_t smem_u32(const void* p) {
    uint32_t a;
    asm("{ .reg .u64 t; cvta.to.shared.u64 t, %1; cvt.u32.u64 %0, t; }" : "=r"(a) : "l"(p));
    return a;
}
__device__ __forceinline__ void ldsm4(uint32_t* r, uint32_t addr) {
    asm volatile("ldmatrix.sync.aligned.m8n8.x4.shared.b16 {%0,%1,%2,%3}, [%4];"
        : "=r"(r[0]), "=r"(r[1]), "=r"(r[2]), "=r"(r[3]) : "r"(addr));
}
__device__ __forceinline__ void mma16816(float* d, const uint32_t* a, uint32_t b0, uint32_t b1) {
    asm volatile("mma.sync.aligned.m16n8k16.row.col.f32.bf16.bf16.f32 "
        "{%0,%1,%2,%3}, {%4,%5,%6,%7}, {%8,%9}, {%0,%1,%2,%3};"
        : "+f"(d[0]), "+f"(d[1]), "+f"(d[2]), "+f"(d[3])
        : "r"(a[0]), "r"(a[1]), "r"(a[2]), "r"(a[3]), "r"(b0), "r"(b1));
}
__device__ __forceinline__ void cp16(uint32_t dst, const void* src) {
    asm volatile("cp.async.cg.shared.global [%0], [%1], 16;" :: "r"(dst), "l"(src));
}
#define CP_COMMIT() asm volatile("cp.async.commit_group;" ::: "memory")
#define CP_WAIT(n)  asm volatile("cp.async.wait_group %0;" :: "n"(n) : "memory")

__device__ __forceinline__ void split_store(bf16* hi, bf16* lo, size_t idx, float v) {
    bf16 h = __float2bfloat16(v);
    hi[idx] = h;
    lo[idx] = __float2bfloat16(v - __bfloat162float(h));
}

// software grid barrier across NBR CTAs (all resident: 1 CTA/SM via smem)
__device__ __forceinline__ void grid_sync() {
    __syncthreads();
    if (threadIdx.x == 0) {
        __threadfence();
        unsigned g = g_bar_gen;
        if (atomicAdd(&g_bar_count, 1u) == (unsigned)(NBR - 1)) {
            g_bar_count = 0;
            __threadfence();
            g_bar_gen = g + 1u;
        } else {
            while (g_bar_gen == g) { __nanosleep(40); }
            __threadfence();
        }
    }
    __syncthreads();
}

// ---------------- xe = tanh(x @ Win^T + bin), split to bf16 hi/lo ----------------
__global__ void embed_kernel(const float* __restrict__ seq,
                             const float* __restrict__ Win,
                             const float* __restrict__ bin) {
    int tok = blockIdx.x;
    __shared__ float xs[KIN];
    if (threadIdx.x < KIN) xs[threadIdx.x] = seq[(size_t)tok*16 + threadIdx.x];
    __syncthreads();
    for (int j = threadIdx.x; j < KST; j += blockDim.x) {
        float s = bin[j];
        const float* wr = Win + j*KIN;
        #pragma unroll
        for (int i = 0; i < KIN; i++) s += xs[i]*wr[i];
        split_store(g_xe_hi, g_xe_lo, (size_t)tok*KST + j, ftanh(s));
    }
}

// ---------------- split-bf16 GEMM: C = act(A @ B^T), tile 128x64, K=512 ----------------
// cp.async 3-stage pipelined A chunks (k=32); B slab staged once.
#define GS_WHI  0
#define GS_WLO  66560
#define GS_A    133120          // 3 bufs x (hi 10240 + lo 10240)
#define GS_ABUF 20480
#define GS_SMEM (GS_A + 3*GS_ABUF)   // 194560
template<int TANH>
__global__ void __launch_bounds__(256) gemm_split(
    const bf16* __restrict__ Ahi, const bf16* __restrict__ Alo,
    const float* __restrict__ B, float* __restrict__ C, int N)
{
    extern __shared__ char sm[];
    uint32_t smu = smem_u32(sm);
    int tid = threadIdx.x;
    int w = tid >> 5, lane = tid & 31;
    int bm = blockIdx.x*128, bn = blockIdx.y*64;

    // stage B slab: 64 rows x 512 k, split fp32 -> hi/lo bf16
    for (int e = tid; e < 64*KST; e += 256) {
        int n = e >> 9, k = e & (KST-1);
        float v = B[(size_t)(bn + n)*KST + k];
        bf16 h = __float2bfloat16(v);
        size_t o = (size_t)n*BSTR + k;
        ((bf16*)(sm + GS_WHI))[o] = h;
        ((bf16*)(sm + GS_WLO))[o] = __float2bfloat16(v - __bfloat162float(h));
    }

    float acc[8][4];
    #pragma unroll
    for (int i = 0; i < 8; i++) { acc[i][0]=0.f; acc[i][1]=0.f; acc[i][2]=0.f; acc[i][3]=0.f; }

    uint32_t a_off = ((uint32_t)(16*w + (lane & 15))*ASTR + ((lane >> 4) << 3)) * 2;
    uint32_t b_row = (lane & 7) + ((lane & 16) >> 1);
    uint32_t b_k8  = (lane & 8);

    // A staging: 128 rows x 32 k, 2 thr/row, each 16 elems via 2x cp16 per array
    int srow = tid >> 1, skc = (tid & 1)*16;
    const bf16* ahp = Ahi + (size_t)(bm + srow)*KST + skc;
    const bf16* alp = Alo + (size_t)(bm + srow)*KST + skc;
    uint32_t sdst = (uint32_t)(srow*ASTR + skc)*2;

    // prologue: chunk 0
    {
        uint32_t d = smu + GS_A + sdst;
        cp16(d,      ahp);      cp16(d + 16,      ahp + 8);
        cp16(d + 10240, alp);   cp16(d + 10240 + 16, alp + 8);
        CP_COMMIT();
    }
    __syncthreads();   // B slab visible

    #pragma unroll 1
    for (int c = 0; c < 16; c++) {
        if (c + 1 < 16) {
            uint32_t d = smu + GS_A + ((c+1)%3)*GS_ABUF + sdst;
            const bf16* ah = ahp + (c+1)*32;
            const bf16* al = alp + (c+1)*32;
            cp16(d, ah);          cp16(d + 16, ah + 8);
            cp16(d + 10240, al);  cp16(d + 10240 + 16, al + 8);
            CP_COMMIT();
            CP_WAIT(1);
        } else {
            CP_WAIT(0);
        }
        __syncthreads();
        uint32_t abase = smu + GS_A + (c%3)*GS_ABUF;
        #pragma unroll
        for (int ks = 0; ks < 2; ks++) {
            uint32_t ah[4], al[4];
            ldsm4(ah, abase + a_off + ks*32);
            ldsm4(al, abase + 10240 + a_off + ks*32);
            uint32_t kb = (uint32_t)(c*32 + ks*16 + b_k8)*2;
            #pragma unroll
            for (int p = 0; p < 4; p++) {
                uint32_t bh[4], bl[4];
                uint32_t bo = (uint32_t)(16*p + b_row)*BSTR*2 + kb;
                ldsm4(bh, smu + GS_WHI + bo);
                ldsm4(bl, smu + GS_WLO + bo);
                mma16816(acc[2*p],   ah, bh[0], bh[1]);
                mma16816(acc[2*p+1], ah, bh[2], bh[3]);
                mma16816(acc[2*p],   ah, bl[0], bl[1]);
                mma16816(acc[2*p+1], ah, bl[2], bl[3]);
                mma16816(acc[2*p],   al, bh[0], bh[1]);
                mma16816(acc[2*p+1], al, bh[2], bh[3]);
            }
        }
    }

    int rowl = bm + 16*w + (lane >> 2);
    #pragma unroll
    for (int nt = 0; nt < 8; nt++) {
        int col = bn + 8*nt + 2*(lane & 3);
        #pragma unroll
        for (int rr = 0; rr < 2; rr++) {
            size_t ro = (size_t)(rowl + 8*rr)*N + col;
            float v0 = acc[nt][2*rr], v1 = acc[nt][2*rr+1];
            if (TANH) { v0 = ftanh(v0); v1 = ftanh(v1); }
            C[ro] = v0; C[ro + 1] = v1;
        }
    }
}

// ---------------- persistent recurrence kernel (warp-MMA, split-bf16, cp.async pipe) ----------------
// 128 CTAs x 256 thr. CTA: b0 = (cta&7)*64 rows, j0 = (cta>>3)*32 state cols.
#define RC_WAHI 0
#define RC_WALO 66560
#define RC_WBHI 133120
#define RC_WBLO 166400
#define RC_A    199680          // 3 bufs x (hi 5120 + lo 5120)
#define RC_ABUF 10240
#define RC_SMEM (RC_A + 3*RC_ABUF)   // 230400
__global__ void __launch_bounds__(256, 1) recur_mma(
    const float* __restrict__ seq, const float* __restrict__ state0,
    const float* __restrict__ Wg, const float* __restrict__ bg,
    const float* __restrict__ Wlin, const float* __restrict__ blin)
{
    extern __shared__ char sm[];
    uint32_t smu = smem_u32(sm);
    int tid = threadIdx.x;
    int w = tid >> 5, lane = tid & 31;
    int cta = blockIdx.x;
    int b0 = (cta & 7)*64;
    int j0 = (cta >> 3)*32;

    // stage Wg slab (64 rows: 32 z + 32 r) and Wlin slab (32 rows), split hi/lo
    for (int e = tid; e < 64*KST; e += 256) {
        int n = e >> 9, k = e & (KST-1);
        int grow = (n < 32) ? (j0 + n) : (KST + j0 + n - 32);
        float v = Wg[(size_t)grow*KST + k];
        bf16 h = __float2bfloat16(v);
        size_t o = (size_t)n*BSTR + k;
        ((bf16*)(sm + RC_WAHI))[o] = h;
        ((bf16*)(sm + RC_WALO))[o] = __float2bfloat16(v - __bfloat162float(h));
    }
    for (int e = tid; e < 32*KST; e += 256) {
        int n = e >> 9, k = e & (KST-1);
        float v = Wlin[(size_t)(j0 + n)*KST + k];
        bf16 h = __float2bfloat16(v);
        size_t o = (size_t)n*BSTR + k;
        ((bf16*)(sm + RC_WBHI))[o] = h;
        ((bf16*)(sm + RC_WBLO))[o] = __float2bfloat16(v - __bfloat162float(h));
    }
    // init h + split
    for (int idx = cta*256 + tid; idx < B_SZ*KST; idx += NBR*256) {
        float h0 = state0[idx & (KST-1)];
        g_h[idx] = h0;
        split_store(g_hs_hi, g_hs_lo, idx, h0);
    }
    grid_sync();

    // per-warp geometry
    int mtA = w & 3, chA = w >> 2;          // phase A: 4 m-tiles x 2 col halves (z|r)
    int mtB = w & 3, coB = (w >> 2)*16;     // phase B: 4 m-tiles x 2 col-16 halves
    uint32_t a_offA = ((uint32_t)(16*mtA + (lane & 15))*ASTR + ((lane >> 4) << 3)) * 2;
    uint32_t b_row = (lane & 7) + ((lane & 16) >> 1);
    uint32_t b_k8  = (lane & 8);

    // A staging: 64 rows x 32 k, 4 thr/row, each 8 elems via 1x cp16 per array
    int srow = tid >> 2, skc = (tid & 3)*8;
    uint32_t sdst = (uint32_t)(srow*ASTR + skc)*2;
    const size_t arow_off = (size_t)(b0 + srow)*KST + skc;

    #pragma unroll 1
    for (int t = 0; t < L_SEQ; ++t) {
        const float* Lxt = g_Lx + (size_t)t*B_SZ*NLX;
        #pragma unroll 1
        for (int s = 1; s <= 4; ++s) {
            const float* hin = (s==1) ? g_h : (s==2 ? g_hA : (s==3 ? g_hB : g_hA));

            // ================= phase A: gate GEMM (z,r) =================
            {
                float acc[4][4];
                #pragma unroll
                for (int i = 0; i < 4; i++) { acc[i][0]=0.f; acc[i][1]=0.f; acc[i][2]=0.f; acc[i][3]=0.f; }
                const bf16* shp = g_hs_hi + arow_off;
                const bf16* slp = g_hs_lo + arow_off;
                {
                    uint32_t d = smu + RC_A + sdst;
                    cp16(d, shp);
                    cp16(d + 5120, slp);
                    CP_COMMIT();
                }
                #pragma unroll 1
                for (int c = 0; c < 16; c++) {
                    if (c + 1 < 16) {
                        uint32_t d = smu + RC_A + ((c+1)%3)*RC_ABUF + sdst;
                        cp16(d,        shp + (c+1)*32);
                        cp16(d + 5120, slp + (c+1)*32);
                        CP_COMMIT();
                        CP_WAIT(1);
                    } else {
                        CP_WAIT(0);
                    }
                    __syncthreads();
                    uint32_t abase = smu + RC_A + (c%3)*RC_ABUF;
                    #pragma unroll
                    for (int ks = 0; ks < 2; ks++) {
                        uint32_t ah[4], al[4];
                        ldsm4(ah, abase + a_offA + ks*32);
                        ldsm4(al, abase + 5120 + a_offA + ks*32);
                        uint32_t kb = (uint32_t)(c*32 + ks*16 + b_k8)*2;
                        #pragma unroll
                        for (int p = 0; p < 2; p++) {
                            uint32_t bh[4], bl[4];
                            uint32_t bo = (uint32_t)(32*chA + 16*p + b_row)*BSTR*2 + kb;
                            ldsm4(bh, smu + RC_WAHI + bo);
                            ldsm4(bl, smu + RC_WALO + bo);
                            mma16816(acc[2*p],   ah, bh[0], bh[1]);
                            mma16816(acc[2*p+1], ah, bh[2], bh[3]);
                            mma16816(acc[2*p],   ah, bl[0], bl[1]);
                            mma16816(acc[2*p+1], ah, bl[2], bl[3]);
                            mma16816(acc[2*p],   al, bh[0], bh[1]);
                            mma16816(acc[2*p+1], al, bh[2], bh[3]);
                        }
                    }
                }
                // gate epilogue
                int rowl = b0 + 16*mtA + (lane >> 2);
                #pragma unroll
                for (int nt = 0; nt < 4; nt++) {
                    int jl = 8*nt + 2*(lane & 3);
                    #pragma unroll
                    for (int rr = 0; rr < 2; rr++) {
                        int row = rowl + 8*rr;
                        const float* lx = Lxt + (size_t)row*NLX;
                        #pragma unroll
                        for (int jj = 0; jj < 2; jj++) {
                            int j = j0 + jl + jj;
                            float a = acc[nt][2*rr + jj];
                            size_t idx = (size_t)row*KST + j;
                            if (chA == 0) {
                                g_zg[idx] = fsigmoid(a + lx[j] + bg[j]);
                            } else {
                                float r = fsigmoid(a + lx[KST + j] + bg[KST + j]);
                                split_store(g_us_hi, g_us_lo, idx, r * hin[idx]);
                            }
                        }
                    }
                }
            }
            grid_sync();

            // ================= phase B: lin GEMM + RK4 =================
            {
                float acc[2][4];
                #pragma unroll
                for (int i = 0; i < 2; i++) { acc[i][0]=0.f; acc[i][1]=0.f; acc[i][2]=0.f; acc[i][3]=0.f; }
                const bf16* shp = g_us_hi + arow_off;
                const bf16* slp = g_us_lo + arow_off;
                {
                    uint32_t d = smu + RC_A + sdst;
                    cp16(d, shp);
                    cp16(d + 5120, slp);
                    CP_COMMIT();
                }
                #pragma unroll 1
                for (int c = 0; c < 16; c++) {
                    if (c + 1 < 16) {
                        uint32_t d = smu + RC_A + ((c+1)%3)*RC_ABUF + sdst;
                        cp16(d,        shp + (c+1)*32);
                        cp16(d + 5120, slp + (c+1)*32);
                        CP_COMMIT();
                        CP_WAIT(1);
                    } else {
                        CP_WAIT(0);
                    }
                    __syncthreads();
                    uint32_t abase = smu + RC_A + (c%3)*RC_ABUF;
                    #pragma unroll
                    for (int ks = 0; ks < 2; ks++) {
                        uint32_t ah[4], al[4];
                        ldsm4(ah, abase + a_offA + ks*32);
                        ldsm4(al, abase + 5120 + a_offA + ks*32);
                        uint32_t kb = (uint32_t)(c*32 + ks*16 + b_k8)*2;
                        uint32_t bh[4], bl[4];
                        uint32_t bo = (uint32_t)(coB + b_row)*BSTR*2 + kb;
                        ldsm4(bh, smu + RC_WBHI + bo);
                        ldsm4(bl, smu + RC_WBLO + bo);
                        mma16816(acc[0], ah, bh[0], bh[1]);
                        mma16816(acc[1], ah, bh[2], bh[3]);
                        mma16816(acc[0], ah, bl[0], bl[1]);
                        mma16816(acc[1], ah, bl[2], bl[3]);
                        mma16816(acc[0], al, bh[0], bh[1]);
                        mma16816(acc[1], al, bh[2], bh[3]);
                    }
                }
                // RK4 epilogue
                int rowl = b0 + 16*mtB + (lane >> 2);
                #pragma unroll
                for (int rr = 0; rr < 2; rr++) {
                    int row = rowl + 8*rr;
                    float dt = (t > 0) ? seq[((size_t)(t-1)*B_SZ + row)*16 + 15] : 0.f;
                    const float* lx = Lxt + (size_t)row*NLX;
                    #pragma unroll
                    for (int nt = 0; nt < 2; nt++) {
                        int jl = coB + 8*nt + 2*(lane & 3);
                        #pragma unroll
                        for (int jj = 0; jj < 2; jj++) {
                            int j = j0 + jl + jj;
                            size_t idx = (size_t)row*KST + j;
                            float hv = hin[idx];
                            float kv = g_zg[idx] * (ftanh(acc[nt][2*rr + jj] + lx[2*KST + j] + blin[j]) - hv);
                            float ht;
                            if (s == 1)      { g_acc[idx]  = kv;      ht = g_h[idx] + dt*0.5f*kv; g_hA[idx] = ht; }
                            else if (s == 2) { g_acc[idx] += 2.f*kv;  ht = g_h[idx] + dt*0.5f*kv; g_hB[idx] = ht; }
                            else if (s == 3) { g_acc[idx] += 2.f*kv;  ht = g_h[idx] + dt*kv;      g_hA[idx] = ht; }
                            else {
                                ht = g_h[idx] + dt*(g_acc[idx] + kv)*(1.f/6.f);
                                g_h[idx] = ht;
                                split_store(g_st_hi, g_st_lo, (size_t)t*B_SZ*KST + idx, ht);
                            }
                            split_store(g_hs_hi, g_hs_lo, idx, ht);
                        }
                    }
                }
            }
            grid_sync();
        }
    }
}

// ---------------- out[1..255] = g_ty @ Ly2^T ----------------
__global__ void yout_kernel(const float* __restrict__ Ly2, float* __restrict__ out) {
    __shared__ float l2s[8*KST];
    int tid = threadIdx.x;
    for (int i = tid; i < 8*KST; i += 256) l2s[i] = Ly2[i];
    __syncthreads();
    int warp = tid >> 5, lane = tid & 31;
    int tok = blockIdx.x*8 + warp;
    const float* tr = g_ty + (size_t)tok*KST;
    float p[8] = {};
    for (int k = lane; k < KST; k += 32) {
        float tv = tr[k];
        #pragma unroll
        for (int o = 0; o < 8; o++) p[o] += tv*l2s[o*KST + k];
    }
    #pragma unroll
    for (int o = 0; o < 8; o++)
        #pragma unroll
        for (int off = 16; off; off >>= 1)
            p[o] += __shfl_xor_sync(0xffffffffu, p[o], off);
    if (lane == 0) {
        float* op = out + (size_t)(tok + B_SZ)*8;
        #pragma unroll
        for (int o = 0; o < 8; o++) op[o] = p[o];
    }
}

// ---------------- out[0] = Ly(h0) broadcast over batch ----------------
__global__ void y0_kernel(const float* __restrict__ state0,
                          const float* __restrict__ Ly1,
                          const float* __restrict__ Ly2,
                          float* __restrict__ out) {
    __shared__ float h0s[KST];
    __shared__ float tys[KST];
    __shared__ float y0s[8];
    int tid = threadIdx.x;
    for (int j = tid; j < KST; j += 256) h0s[j] = state0[j];
    __syncthreads();
    for (int j = tid; j < KST; j += 256) {
        float s = 0.f;
        const float* lr = Ly1 + (size_t)j*KST;
        for (int k = 0; k < KST; k++) s += h0s[k]*lr[k];
        tys[j] = tanhf(s);
    }
    __syncthreads();
    if (tid < 8) {
        float s = 0.f;
        const float* lr = Ly2 + (size_t)tid*KST;
        for (int k = 0; k < KST; k++) s += tys[k]*lr[k];
        y0s[tid] = s;
    }
    __syncthreads();
    for (int i = tid; i < B_SZ*8; i += 256) out[i] = y0s[i & 7];
}

// ---------------- launch ----------------
extern "C" void kernel_launch(void* const* d_in, const int* in_sizes, int n_in,
                              void* d_out, int out_size) {
    const float* seq    = (const float*)d_in[0];
    const float* state0 = (const float*)d_in[1];
    const float* Win    = (const float*)d_in[2];
    const float* bin    = (const float*)d_in[3];
    const float* Wx     = (const float*)d_in[4];
    const float* Wg     = (const float*)d_in[5];
    const float* bg     = (const float*)d_in[6];
    const float* Wlin   = (const float*)d_in[7];
    const float* blin   = (const float*)d_in[8];
    const float* Ly1    = (const float*)d_in[9];
    const float* Ly2    = (const float*)d_in[10];
    float* out = (float*)d_out;

    bf16 *xeh, *xel, *sth, *stl;
    float *Lx, *ty;
    cudaGetSymbolAddress((void**)&xeh, g_xe_hi);
    cudaGetSymbolAddress((void**)&xel, g_xe_lo);
    cudaGetSymbolAddress((void**)&sth, g_st_hi);
    cudaGetSymbolAddress((void**)&stl, g_st_lo);
    cudaGetSymbolAddress((void**)&Lx,  g_Lx);
    cudaGetSymbolAddress((void**)&ty,  g_ty);

    cudaFuncSetAttribute(recur_mma, cudaFuncAttributeMaxDynamicSharedMemorySize, RC_SMEM);
    cudaFuncSetAttribute(gemm_split<0>, cudaFuncAttributeMaxDynamicSharedMemorySize, GS_SMEM);
    cudaFuncSetAttribute(gemm_split<1>, cudaFuncAttributeMaxDynamicSharedMemorySize, GS_SMEM);

    embed_kernel<<<NTOK, 128>>>(seq, Win, bin);
    gemm_split<0><<<dim3(NTOK/128, NLX/64), 256, GS_SMEM>>>(xeh, xel, Wx, Lx, NLX);

    recur_mma<<<NBR, 256, RC_SMEM>>>(seq, state0, Wg, bg, Wlin, blin);

    gemm_split<1><<<dim3((NTOK - B_SZ)/128, KST/64), 256, GS_SMEM>>>(sth, stl, Ly1, ty, KST);
    yout_kernel<<<(NTOK - B_SZ)/8, 256>>>(Ly2, out);
    y0_kernel<<<1, 256>>>(state0, Ly1, Ly2, out);
}